// round 8
// baseline (speedup 1.0000x reference)
#include <cuda_runtime.h>
#include <cuda_bf16.h>
#include <cstdint>

#define CODES 1024
#define CDIM  256
#define HW    1024
#define NPIX  65536
#define NCHUNK 8            // 1024 codes / 128
#define NTILE  512          // 65536 px / 128

// ---------------- static scratch ----------------
__device__ __align__(1024) unsigned char g_wb[NCHUNK * 65536]; // bf16 B images (swizzled)
__device__ __align__(1024) unsigned char g_xb[NTILE * 65536];  // bf16 A images (swizzled)
__device__ __align__(1024) float g_xT[(size_t)NPIX * CDIM];    // fp32 x, pixel-major (64MB)
__device__ float g_wsq[CODES];
__device__ float g_pmax[128];
__device__ float g_xx[NPIX];
__device__ float g_sx[NPIX];
__device__ int   g_cand[NPIX * 32];
__device__ int   g_cnt[NPIX];
__device__ int   g_idx[NPIX];
__device__ int   g_queue[NPIX];
__device__ int   g_qcnt;

// ---------------- helpers ----------------
__device__ __forceinline__ uint32_t smem_u32(const void *p) {
    uint32_t a;
    asm("{ .reg .u64 t; cvta.to.shared.u64 t, %1; cvt.u32.u64 %0, t; }" : "=r"(a) : "l"(p));
    return a;
}
__device__ __forceinline__ void cp16(uint32_t dst, const void *src) {
    asm volatile("cp.async.cg.shared.global [%0], [%1], 16;" :: "r"(dst), "l"(src) : "memory");
}
#define CP_COMMIT() asm volatile("cp.async.commit_group;" ::: "memory")
#define CP_WAIT1()  asm volatile("cp.async.wait_group 1;" ::: "memory")
#define CP_WAIT0()  asm volatile("cp.async.wait_group 0;" ::: "memory")

__device__ __forceinline__ uint32_t packbf(float lo, float hi) {
    uint32_t r;
    asm("cvt.rn.bf16x2.f32 %0, %1, %2;" : "=r"(r) : "f"(hi), "f"(lo));  // r = hi<<16 | lo
    return r;
}
// image layout: 128 rows x 256 bf16 k-major, rows of 512B = 32 16B-chunks,
// chunk swizzle: stored chunk index = chunk ^ (row & 7)  -> ldmatrix conflict-free
__device__ __forceinline__ uint32_t img_off(int row, int chunk) {
    return (uint32_t)row * 512u + (uint32_t)((chunk ^ (row & 7)) << 4);
}

__device__ __forceinline__ void ldsm_x4(uint32_t &r0, uint32_t &r1, uint32_t &r2, uint32_t &r3,
                                        uint32_t addr) {
    asm volatile("ldmatrix.sync.aligned.m8n8.x4.shared.b16 {%0,%1,%2,%3}, [%4];"
                 : "=r"(r0), "=r"(r1), "=r"(r2), "=r"(r3) : "r"(addr));
}
__device__ __forceinline__ void mma16816(float *d, uint32_t a0, uint32_t a1, uint32_t a2,
                                         uint32_t a3, uint32_t b0, uint32_t b1) {
    asm volatile("mma.sync.aligned.m16n8k16.row.col.f32.bf16.bf16.f32 "
                 "{%0,%1,%2,%3}, {%4,%5,%6,%7}, {%8,%9}, {%0,%1,%2,%3};"
                 : "+f"(d[0]), "+f"(d[1]), "+f"(d[2]), "+f"(d[3])
                 : "r"(a0), "r"(a1), "r"(a2), "r"(a3), "r"(b0), "r"(b1));
}

// =====================================================================
// prep_w: exact wsq, bf16 swizzled B images, per-block max|w|, zero queue
// grid 128 x 256 (8 codes/block, one warp per code)
// =====================================================================
__global__ void prep_w(const float *__restrict__ w) {
    __shared__ float wm[8];
    if (blockIdx.x == 0 && threadIdx.x == 0) g_qcnt = 0;
    int wid = threadIdx.x >> 5, lane = threadIdx.x & 31;
    int code = blockIdx.x * 8 + wid;
    const float *row = w + code * CDIM;
    float s = 0.f, pm = 0.f;
#pragma unroll
    for (int j = 0; j < 8; j++) {
        float v = row[lane + 32 * j];
        s = __fmaf_rn(v, v, s);
        pm = fmaxf(pm, fabsf(v));
    }
#pragma unroll
    for (int o = 16; o; o >>= 1) {
        s += __shfl_xor_sync(0xffffffffu, s, o);
        pm = fmaxf(pm, __shfl_xor_sync(0xffffffffu, pm, o));
    }
    if (lane == 0) { g_wsq[code] = s; wm[wid] = pm; }
    float f[8];
#pragma unroll
    for (int j = 0; j < 8; j++) f[j] = row[lane * 8 + j];
    uint4 v;
    v.x = packbf(f[0], f[1]); v.y = packbf(f[2], f[3]);
    v.z = packbf(f[4], f[5]); v.w = packbf(f[6], f[7]);
    int chunk = code >> 7, lr = code & 127;
    *(uint4 *)(g_wb + chunk * 65536 + img_off(lr, lane)) = v;
    __syncthreads();
    if (threadIdx.x == 0) {
        float m = 0.f;
        for (int i = 0; i < 8; i++) m = fmaxf(m, wm[i]);
        g_pmax[blockIdx.x] = m;
    }
}

// =====================================================================
// prep_x: per 128-pixel tile: transpose+convert x -> bf16 swizzled A image,
//         fp32 pixel-major g_xT, exact sequential xx and sum|x|.
// grid 512 x 256.
// =====================================================================
#define XP 130
__global__ __launch_bounds__(256) void prep_x(const float *__restrict__ x) {
    extern __shared__ float sm[];
    const int tile = blockIdx.x;
    const int b = tile >> 3, hw0 = (tile & 7) * 128;
    const int tid = threadIdx.x;
    unsigned char *dst = g_xb + (size_t)tile * 65536;
    float *xtd = g_xT + (size_t)tile * 128 * CDIM;
    float xxa = 0.f, sxa = 0.f;

    for (int h = 0; h < 2; h++) {
        const float *src = x + (size_t)b * CDIM * HW + (size_t)(h * 128) * HW + hw0;
#pragma unroll
        for (int it = 0; it < 64; it++) {
            int idx = tid + 256 * it;
            int kk = idx >> 7, p = idx & 127;
            sm[kk * XP + p] = src[(size_t)kk * HW + p];
        }
        __syncthreads();
        if (tid < 128) {
            for (int kk = 0; kk < 128; kk++) {
                float v = sm[kk * XP + tid];
                xxa = __fadd_rn(xxa, __fmul_rn(v, v));
                sxa = __fadd_rn(sxa, fabsf(v));
            }
        }
        // fp32 transpose out: g_xT[pix][h*128 + k]  (coalesced float4 per warp)
        {
            int k4 = tid & 31;                  // 32 float4 per pixel-half
            for (int pp = tid >> 5; pp < 128; pp += 8) {
                float4 v4;
                v4.x = sm[(k4 * 4 + 0) * XP + pp];
                v4.y = sm[(k4 * 4 + 1) * XP + pp];
                v4.z = sm[(k4 * 4 + 2) * XP + pp];
                v4.w = sm[(k4 * 4 + 3) * XP + pp];
                *(float4 *)(xtd + (size_t)pp * CDIM + h * 128 + k4 * 4) = v4;
            }
        }
        // bf16 swizzled A image
        int p = tid & 127;
#pragma unroll
        for (int it = 0; it < 8; it++) {
            int oct = (tid >> 7) * 8 + it;         // 0..15 within half
            float f[8];
#pragma unroll
            for (int j = 0; j < 8; j++) f[j] = sm[(oct * 8 + j) * XP + p];
            uint4 v;
            v.x = packbf(f[0], f[1]); v.y = packbf(f[2], f[3]);
            v.z = packbf(f[4], f[5]); v.w = packbf(f[6], f[7]);
            *(uint4 *)(dst + img_off(p, h * 16 + oct)) = v;
        }
        __syncthreads();
    }
    if (tid < 128) {
        g_xx[tile * 128 + tid] = xxa;
        g_sx[tile * 128 + tid] = sxa;
    }
}

// =====================================================================
// mma_kernel: warp tiling 4(px-groups of 32) x 2(N-halves of 64 codes).
//   Per ks: 2 A-LDSM + 4 B-LDSM + 16 MMA  (was 9 LDSM + 16 MMA).
//   Double-buffered B. Epilogue: per-warp running min + candidate superset
//   (per-warp min >= global min -> still a superset). cnt==1 finalized.
// grid 512 x 256
// =====================================================================
#define SM_WSQ 0
#define SM_CNT 4096
#define SM_A   8192
#define SM_B0  73728
#define SM_B1  139264
#define SMEM_MMA 204800

__device__ __forceinline__ void copy_img(uint32_t dst, const unsigned char *src, int tid) {
#pragma unroll
    for (int i = 0; i < 16; i++) {
        int c = tid + 256 * i;        // 4096 chunks of 16B
        cp16(dst + (uint32_t)c * 16u, src + (size_t)c * 16u);
    }
}

__global__ __launch_bounds__(256, 1) void mma_kernel(float *__restrict__ out_idxf) {
    extern __shared__ char smc[];
    uint32_t sb = smem_u32(smc);
    float *wsq_s = (float *)(smc + SM_WSQ);
    int *cnt_s = (int *)(smc + SM_CNT);
    const int tid = threadIdx.x, warp = tid >> 5, lane = tid & 31;
    const int tile = blockIdx.x;
    const int wM = warp & 3;        // pixel group: 32 px
    const int wN = warp >> 2;       // code half: 64 codes
    const int m0 = wM * 32;

    copy_img(sb + SM_A, g_xb + (size_t)tile * 65536, tid);
    copy_img(sb + SM_B0, g_wb, tid);
    CP_COMMIT();

    for (int i = tid; i < CODES; i += 256) wsq_s[i] = g_wsq[i];
    if (tid < 128) cnt_s[tid] = 0;
    if (tid == 0) {
        float m = 0.f;
        for (int i = 0; i < 128; i++) m = fmaxf(m, g_pmax[i]);
        ((float *)(smc + SM_CNT))[130] = m;   // stash wmax after counters
    }
    __syncthreads();
    const float wmax = ((float *)(smc + SM_CNT))[130];

    // 4 pixel rows per thread: [f][0] = m0+f*16+(lane>>2), [f][1] = +8
    const int pr = lane >> 2;
    float xxv[2][2], THv[2][2];
    float runmin[2][2];
#pragma unroll
    for (int f = 0; f < 2; f++)
#pragma unroll
        for (int r = 0; r < 2; r++) {
            int pix = tile * 128 + m0 + f * 16 + r * 8 + pr;
            xxv[f][r] = g_xx[pix];
            THv[f][r] = __fmaf_rn(g_sx[pix] * wmax, 0.0172f, 1e-3f);
            runmin[f][r] = __int_as_float(0x7f800000);
        }

    // ldmatrix addressing
    const int mat = lane >> 3, r7 = lane & 7;
    const int a_row0 = m0 + r7 + ((mat & 1) << 3);
    const int a_cadd = mat >> 1;
    const uint32_t a_base0 = sb + SM_A + (uint32_t)a_row0 * 512u;       // f=0
    const uint32_t a_base1 = a_base0 + 16u * 512u;                      // f=1
    const int b_rowoff = r7 + ((mat >> 1) << 3);                        // within 16-code group
    const int b_cadd = mat & 1;
    const uint32_t b_roff = (uint32_t)(wN * 64) * 512u + (uint32_t)b_rowoff * 512u;

    for (int c = 0; c < NCHUNK; c++) {
        if (c < 7) {
            copy_img(sb + (((c + 1) & 1) ? SM_B1 : SM_B0), g_wb + (size_t)(c + 1) * 65536, tid);
            CP_COMMIT();
            CP_WAIT1();
        } else {
            CP_WAIT0();
        }
        __syncthreads();

        const uint32_t b_base = sb + ((c & 1) ? SM_B1 : SM_B0) + b_roff;

        float acc[2][8][4];
#pragma unroll
        for (int f = 0; f < 2; f++)
#pragma unroll
            for (int nb = 0; nb < 8; nb++)
#pragma unroll
                for (int j = 0; j < 4; j++) acc[f][nb][j] = 0.f;

#pragma unroll
        for (int ks = 0; ks < 16; ks++) {
            const uint32_t koff = (uint32_t)(((2 * ks + a_cadd) ^ r7) << 4);
            const uint32_t koffb = (uint32_t)(((2 * ks + b_cadd) ^ r7) << 4);
            uint32_t a00, a01, a02, a03, a10, a11, a12, a13;
            ldsm_x4(a00, a01, a02, a03, a_base0 + koff);
            ldsm_x4(a10, a11, a12, a13, a_base1 + koff);
#pragma unroll
            for (int g = 0; g < 4; g++) {
                uint32_t b0, b1, b2, b3;
                ldsm_x4(b0, b1, b2, b3, b_base + (uint32_t)(g * 8192) + koffb);
                mma16816(acc[0][2 * g],     a00, a01, a02, a03, b0, b1);
                mma16816(acc[0][2 * g + 1], a00, a01, a02, a03, b2, b3);
                mma16816(acc[1][2 * g],     a10, a11, a12, a13, b0, b1);
                mma16816(acc[1][2 * g + 1], a10, a11, a12, a13, b2, b3);
            }
        }

        // ---- epilogue ----
        const int ncol = 2 * (lane & 3);
        const int code0 = c * 128 + wN * 64 + ncol;
        float lm[2][2];
        lm[0][0] = lm[0][1] = lm[1][0] = lm[1][1] = __int_as_float(0x7f800000);
#pragma unroll
        for (int f = 0; f < 2; f++)
#pragma unroll
            for (int nb = 0; nb < 8; nb++) {
                const float *wq = wsq_s + c * 128 + wN * 64 + nb * 8 + ncol;
                float s;
                s = __fadd_rn(__fmaf_rn(-2.f, acc[f][nb][0], xxv[f][0]), wq[0]); acc[f][nb][0] = s; lm[f][0] = fminf(lm[f][0], s);
                s = __fadd_rn(__fmaf_rn(-2.f, acc[f][nb][1], xxv[f][0]), wq[1]); acc[f][nb][1] = s; lm[f][0] = fminf(lm[f][0], s);
                s = __fadd_rn(__fmaf_rn(-2.f, acc[f][nb][2], xxv[f][1]), wq[0]); acc[f][nb][2] = s; lm[f][1] = fminf(lm[f][1], s);
                s = __fadd_rn(__fmaf_rn(-2.f, acc[f][nb][3], xxv[f][1]), wq[1]); acc[f][nb][3] = s; lm[f][1] = fminf(lm[f][1], s);
            }
#pragma unroll
        for (int o = 1; o <= 2; o <<= 1)
#pragma unroll
            for (int f = 0; f < 2; f++)
#pragma unroll
                for (int r = 0; r < 2; r++)
                    lm[f][r] = fminf(lm[f][r], __shfl_xor_sync(0xffffffffu, lm[f][r], o));
#pragma unroll
        for (int f = 0; f < 2; f++)
#pragma unroll
            for (int r = 0; r < 2; r++)
                runmin[f][r] = fminf(runmin[f][r], lm[f][r]);

#pragma unroll
        for (int f = 0; f < 2; f++)
#pragma unroll
            for (int r = 0; r < 2; r++) {
                const float th = runmin[f][r] + THv[f][r];
                const int pxl = m0 + f * 16 + r * 8 + pr;
                const int pix = tile * 128 + pxl;
#pragma unroll
                for (int nb = 0; nb < 8; nb++) {
                    int cb = code0 + nb * 8;
                    float s0 = acc[f][nb][2 * r], s1 = acc[f][nb][2 * r + 1];
                    if (s0 <= th) {
                        int sl = atomicAdd(&cnt_s[pxl], 1);
                        if (sl < 32) g_cand[(size_t)pix * 32 + sl] = cb;
                    }
                    if (s1 <= th) {
                        int sl = atomicAdd(&cnt_s[pxl], 1);
                        if (sl < 32) g_cand[(size_t)pix * 32 + sl] = cb + 1;
                    }
                }
            }
        __syncthreads();
    }

    if (tid < 128) {
        int pix = tile * 128 + tid;
        int cnt = cnt_s[tid];
        g_cnt[pix] = cnt;
        if (cnt == 1) {
            int cidx = g_cand[(size_t)pix * 32];
            g_idx[pix] = cidx;
            out_idxf[pix] = (float)cidx;
        } else {
            int q = atomicAdd(&g_qcnt, 1);
            g_queue[q] = pix;
        }
    }
}

// =====================================================================
// rescore2: warp per queued pixel, one candidate per lane, exact fp32
//   chain (sequential ascending k). x from pixel-major g_xT.
// grid 512 x 256
// =====================================================================
__global__ __launch_bounds__(256) void rescore2(const float *__restrict__ w,
                                                float *__restrict__ out_idxf) {
    const int lane = threadIdx.x & 31;
    const int gwarp = (blockIdx.x * blockDim.x + threadIdx.x) >> 5;
    const int nwarp = (gridDim.x * blockDim.x) >> 5;
    const int total = g_qcnt;
    const float INF = __int_as_float(0x7f800000);

    for (int q = gwarp; q < total; q += nwarp) {
        int pix = g_queue[q];
        int cnt = g_cnt[pix];
        float xxp = g_xx[pix];
        const float4 *xb4 = (const float4 *)(g_xT + (size_t)pix * CDIM);

        float bestd = INF;
        int besti = CODES;
        int nloop = (cnt > 32) ? 32 : 1;   // overflow -> stripe all 1024 codes

        for (int t = 0; t < nloop; t++) {
            int cidx;
            bool active;
            if (cnt > 32) { cidx = t * 32 + lane; active = true; }
            else          { cidx = (lane < cnt) ? g_cand[(size_t)pix * 32 + lane] : 0; active = (lane < cnt); }

            const float4 *wr = (const float4 *)(w + (size_t)cidx * CDIM);
            float dot = 0.f;
#pragma unroll 8
            for (int qq = 0; qq < 64; qq++) {
                float4 wv = wr[qq];
                float4 xv = xb4[qq];
                dot = __fmaf_rn(xv.x, wv.x, dot);
                dot = __fmaf_rn(xv.y, wv.y, dot);
                dot = __fmaf_rn(xv.z, wv.z, dot);
                dot = __fmaf_rn(xv.w, wv.w, dot);
            }
            float d = __fadd_rn(__fmaf_rn(-2.f, dot, xxp), g_wsq[cidx]);
            if (active && (d < bestd || (d == bestd && cidx < besti))) { bestd = d; besti = cidx; }
        }
#pragma unroll
        for (int o = 16; o; o >>= 1) {
            float od = __shfl_xor_sync(0xffffffffu, bestd, o);
            int   oi = __shfl_xor_sync(0xffffffffu, besti, o);
            if (od < bestd || (od == bestd && oi < besti)) { bestd = od; besti = oi; }
        }
        if (lane == 0) {
            g_idx[pix] = besti;
            out_idxf[pix] = (float)besti;
        }
    }
}

// =====================================================================
// gather: quantized = weight[idx], ste = (q - x) + x
// =====================================================================
__global__ __launch_bounds__(256)
void gather_kernel(const float *__restrict__ x, const float *__restrict__ w,
                   float *__restrict__ out) {
    const int b = blockIdx.y;
    const int c0 = blockIdx.x * 32;
    const int hw4 = threadIdx.x * 4;

    int4 rows = *(const int4 *)&g_idx[b * HW + hw4];
    const float *xb = x + (size_t)b * CDIM * HW + hw4;
    float *qo = out + (size_t)b * CDIM * HW + hw4;
    float *so = out + (size_t)NPIX * CDIM + (size_t)b * CDIM * HW + hw4;
    const float *w0 = w + (size_t)rows.x * CDIM;
    const float *w1 = w + (size_t)rows.y * CDIM;
    const float *w2 = w + (size_t)rows.z * CDIM;
    const float *w3 = w + (size_t)rows.w * CDIM;

#pragma unroll 4
    for (int c = c0; c < c0 + 32; c++) {
        float4 qv;
        qv.x = w0[c]; qv.y = w1[c]; qv.z = w2[c]; qv.w = w3[c];
        float4 xv = *(const float4 *)(xb + (size_t)c * HW);
        *(float4 *)(qo + (size_t)c * HW) = qv;
        float4 sv;
        sv.x = __fadd_rn(__fsub_rn(qv.x, xv.x), xv.x);
        sv.y = __fadd_rn(__fsub_rn(qv.y, xv.y), xv.y);
        sv.z = __fadd_rn(__fsub_rn(qv.z, xv.z), xv.z);
        sv.w = __fadd_rn(__fsub_rn(qv.w, xv.w), xv.w);
        *(float4 *)(so + (size_t)c * HW) = sv;
    }
}

// =====================================================================
extern "C" void kernel_launch(void *const *d_in, const int *in_sizes, int n_in,
                              void *d_out, int out_size) {
    const float *x = (const float *)d_in[0];
    const float *w = (const float *)d_in[1];
    if (n_in >= 2 && in_sizes[0] == CODES * CDIM && in_sizes[1] == NPIX * CDIM) {
        const float *tmp = x; x = w; w = tmp;
    }
    float *out = (float *)d_out;
    float *out_idxf = out + 2 * (size_t)NPIX * CDIM;

    cudaFuncSetAttribute(prep_x, cudaFuncAttributeMaxDynamicSharedMemorySize, 128 * XP * 4);
    cudaFuncSetAttribute(mma_kernel, cudaFuncAttributeMaxDynamicSharedMemorySize, SMEM_MMA);

    prep_w<<<128, 256>>>(w);
    prep_x<<<512, 256, 128 * XP * 4>>>(x);
    mma_kernel<<<512, 256, SMEM_MMA>>>(out_idxf);
    rescore2<<<512, 256>>>(w, out_idxf);
    gather_kernel<<<dim3(8, 64), 256>>>(x, w, out);
}

// round 9
// speedup vs baseline: 1.6560x; 1.6560x over previous
#include <cuda_runtime.h>
#include <cuda_fp16.h>
#include <cstdint>

#define CODES 1024
#define CDIM  256
#define HW    1024
#define NPIX  65536
#define NCHUNK 8            // 1024 codes / 128
#define NTILE  512          // 65536 px / 128

// ---------------- static scratch ----------------
__device__ __align__(1024) unsigned char g_wb[NCHUNK * 65536]; // fp16 B images (swizzled)
__device__ __align__(1024) unsigned char g_xb[NTILE * 65536];  // fp16 A images (swizzled)
__device__ __align__(1024) float g_xT[(size_t)NPIX * CDIM];    // fp32 x, pixel-major (64MB)
__device__ float g_wsq[CODES];
__device__ float g_pmax[128];
__device__ float g_xx[NPIX];
__device__ float g_sx[NPIX];
__device__ int   g_cand[NPIX * 32];
__device__ int   g_cnt[NPIX];
__device__ int   g_idx[NPIX];
__device__ int   g_queue[NPIX];
__device__ int   g_qcnt;

// ---------------- helpers ----------------
__device__ __forceinline__ uint32_t smem_u32(const void *p) {
    uint32_t a;
    asm("{ .reg .u64 t; cvta.to.shared.u64 t, %1; cvt.u32.u64 %0, t; }" : "=r"(a) : "l"(p));
    return a;
}
__device__ __forceinline__ void cp16(uint32_t dst, const void *src) {
    asm volatile("cp.async.cg.shared.global [%0], [%1], 16;" :: "r"(dst), "l"(src) : "memory");
}
#define CP_COMMIT() asm volatile("cp.async.commit_group;" ::: "memory")
#define CP_WAIT1()  asm volatile("cp.async.wait_group 1;" ::: "memory")
#define CP_WAIT0()  asm volatile("cp.async.wait_group 0;" ::: "memory")

__device__ __forceinline__ uint32_t packh(float lo, float hi) {
    uint32_t r;
    asm("cvt.rn.f16x2.f32 %0, %1, %2;" : "=r"(r) : "f"(hi), "f"(lo));  // r = hi<<16 | lo
    return r;
}
// image layout: 128 rows x 256 fp16 k-major, rows of 512B = 32 16B-chunks,
// chunk swizzle: stored chunk index = chunk ^ (row & 7)  -> ldmatrix conflict-free
__device__ __forceinline__ uint32_t img_off(int row, int chunk) {
    return (uint32_t)row * 512u + (uint32_t)((chunk ^ (row & 7)) << 4);
}

__device__ __forceinline__ void ldsm_x4(uint32_t &r0, uint32_t &r1, uint32_t &r2, uint32_t &r3,
                                        uint32_t addr) {
    asm volatile("ldmatrix.sync.aligned.m8n8.x4.shared.b16 {%0,%1,%2,%3}, [%4];"
                 : "=r"(r0), "=r"(r1), "=r"(r2), "=r"(r3) : "r"(addr));
}
__device__ __forceinline__ void mma16816(float *d, uint32_t a0, uint32_t a1, uint32_t a2,
                                         uint32_t a3, uint32_t b0, uint32_t b1) {
    asm volatile("mma.sync.aligned.m16n8k16.row.col.f32.f16.f16.f32 "
                 "{%0,%1,%2,%3}, {%4,%5,%6,%7}, {%8,%9}, {%0,%1,%2,%3};"
                 : "+f"(d[0]), "+f"(d[1]), "+f"(d[2]), "+f"(d[3])
                 : "r"(a0), "r"(a1), "r"(a2), "r"(a3), "r"(b0), "r"(b1));
}

// =====================================================================
// prep_w: exact wsq, fp16 swizzled B images, per-block max|w|, zero queue
// grid 128 x 256 (8 codes/block, one warp per code)
// =====================================================================
__global__ void prep_w(const float *__restrict__ w) {
    __shared__ float wm[8];
    if (blockIdx.x == 0 && threadIdx.x == 0) g_qcnt = 0;
    int wid = threadIdx.x >> 5, lane = threadIdx.x & 31;
    int code = blockIdx.x * 8 + wid;
    const float *row = w + code * CDIM;
    float s = 0.f, pm = 0.f;
#pragma unroll
    for (int j = 0; j < 8; j++) {
        float v = row[lane + 32 * j];
        s = __fmaf_rn(v, v, s);
        pm = fmaxf(pm, fabsf(v));
    }
#pragma unroll
    for (int o = 16; o; o >>= 1) {
        s += __shfl_xor_sync(0xffffffffu, s, o);
        pm = fmaxf(pm, __shfl_xor_sync(0xffffffffu, pm, o));
    }
    if (lane == 0) { g_wsq[code] = s; wm[wid] = pm; }
    float f[8];
#pragma unroll
    for (int j = 0; j < 8; j++) f[j] = row[lane * 8 + j];
    uint4 v;
    v.x = packh(f[0], f[1]); v.y = packh(f[2], f[3]);
    v.z = packh(f[4], f[5]); v.w = packh(f[6], f[7]);
    int chunk = code >> 7, lr = code & 127;
    *(uint4 *)(g_wb + chunk * 65536 + img_off(lr, lane)) = v;
    __syncthreads();
    if (threadIdx.x == 0) {
        float m = 0.f;
        for (int i = 0; i < 8; i++) m = fmaxf(m, wm[i]);
        g_pmax[blockIdx.x] = m;
    }
}

// =====================================================================
// prep_x: per 128-pixel tile: transpose+convert x -> fp16 swizzled A image,
//         fp32 pixel-major g_xT, exact sequential xx and sum|x|.
// grid 512 x 256.
// =====================================================================
#define XP 130
__global__ __launch_bounds__(256) void prep_x(const float *__restrict__ x) {
    extern __shared__ float sm[];
    const int tile = blockIdx.x;
    const int b = tile >> 3, hw0 = (tile & 7) * 128;
    const int tid = threadIdx.x;
    unsigned char *dst = g_xb + (size_t)tile * 65536;
    float *xtd = g_xT + (size_t)tile * 128 * CDIM;
    float xxa = 0.f, sxa = 0.f;

    for (int h = 0; h < 2; h++) {
        const float *src = x + (size_t)b * CDIM * HW + (size_t)(h * 128) * HW + hw0;
#pragma unroll
        for (int it = 0; it < 64; it++) {
            int idx = tid + 256 * it;
            int kk = idx >> 7, p = idx & 127;
            sm[kk * XP + p] = src[(size_t)kk * HW + p];
        }
        __syncthreads();
        if (tid < 128) {
            for (int kk = 0; kk < 128; kk++) {
                float v = sm[kk * XP + tid];
                xxa = __fadd_rn(xxa, __fmul_rn(v, v));
                sxa = __fadd_rn(sxa, fabsf(v));
            }
        }
        // fp32 transpose out: g_xT[pix][h*128 + k]
        {
            int k4 = tid & 31;
            for (int pp = tid >> 5; pp < 128; pp += 8) {
                float4 v4;
                v4.x = sm[(k4 * 4 + 0) * XP + pp];
                v4.y = sm[(k4 * 4 + 1) * XP + pp];
                v4.z = sm[(k4 * 4 + 2) * XP + pp];
                v4.w = sm[(k4 * 4 + 3) * XP + pp];
                *(float4 *)(xtd + (size_t)pp * CDIM + h * 128 + k4 * 4) = v4;
            }
        }
        // fp16 swizzled A image
        int p = tid & 127;
#pragma unroll
        for (int it = 0; it < 8; it++) {
            int oct = (tid >> 7) * 8 + it;
            float f[8];
#pragma unroll
            for (int j = 0; j < 8; j++) f[j] = sm[(oct * 8 + j) * XP + p];
            uint4 v;
            v.x = packh(f[0], f[1]); v.y = packh(f[2], f[3]);
            v.z = packh(f[4], f[5]); v.w = packh(f[6], f[7]);
            *(uint4 *)(dst + img_off(p, h * 16 + oct)) = v;
        }
        __syncthreads();
    }
    if (tid < 128) {
        g_xx[tile * 128 + tid] = xxa;
        g_sx[tile * 128 + tid] = sxa;
    }
}

// =====================================================================
// mma_kernel: warp tiling 4(px-groups of 32) x 2(N-halves of 64 codes).
//   Per ks: 2 A-LDSM + 4 B-LDSM + 16 MMA. Double-buffered B.
//   Pixel-GLOBAL runmin shared across warps via smem atomicMin (scores>0,
//   int-bit compare order-preserving) -> tight superset thresholds.
// grid 512 x 256
// =====================================================================
#define SM_WSQ 0
#define SM_CNT 4096
#define SM_RUN 5120
#define SM_A   8192
#define SM_B0  73728
#define SM_B1  139264
#define SMEM_MMA 204800

__device__ __forceinline__ void copy_img(uint32_t dst, const unsigned char *src, int tid) {
#pragma unroll
    for (int i = 0; i < 16; i++) {
        int c = tid + 256 * i;        // 4096 chunks of 16B
        cp16(dst + (uint32_t)c * 16u, src + (size_t)c * 16u);
    }
}

__global__ __launch_bounds__(256, 1) void mma_kernel(float *__restrict__ out_idxf) {
    extern __shared__ char smc[];
    uint32_t sb = smem_u32(smc);
    float *wsq_s = (float *)(smc + SM_WSQ);
    int *cnt_s = (int *)(smc + SM_CNT);
    int *run_s = (int *)(smc + SM_RUN);
    const int tid = threadIdx.x, warp = tid >> 5, lane = tid & 31;
    const int tile = blockIdx.x;
    const int wM = warp & 3;        // pixel group: 32 px
    const int wN = warp >> 2;       // code half: 64 codes
    const int m0 = wM * 32;

    copy_img(sb + SM_A, g_xb + (size_t)tile * 65536, tid);
    copy_img(sb + SM_B0, g_wb, tid);
    CP_COMMIT();

    for (int i = tid; i < CODES; i += 256) wsq_s[i] = g_wsq[i];
    if (tid < 128) {
        cnt_s[tid] = 0;
        run_s[tid] = 0x7f800000;           // +inf
    }
    if (tid == 0) {
        float m = 0.f;
        for (int i = 0; i < 128; i++) m = fmaxf(m, g_pmax[i]);
        ((float *)(smc + SM_CNT))[130] = m;
    }
    __syncthreads();
    const float wmax = ((float *)(smc + SM_CNT))[130];

    // 4 pixel rows per thread: [f][r] = m0 + f*16 + r*8 + (lane>>2)
    const int pr = lane >> 2;
    float xxv[2][2], THv[2][2];
#pragma unroll
    for (int f = 0; f < 2; f++)
#pragma unroll
        for (int r = 0; r < 2; r++) {
            int pix = tile * 128 + m0 + f * 16 + r * 8 + pr;
            xxv[f][r] = g_xx[pix];
            THv[f][r] = __fmaf_rn(g_sx[pix] * wmax, 0.006f, 4e-4f);   // fp16 bound, 1.5x safety
        }

    // ldmatrix addressing
    const int mat = lane >> 3, r7 = lane & 7;
    const int a_row0 = m0 + r7 + ((mat & 1) << 3);
    const int a_cadd = mat >> 1;
    const uint32_t a_base0 = sb + SM_A + (uint32_t)a_row0 * 512u;       // f=0
    const uint32_t a_base1 = a_base0 + 16u * 512u;                      // f=1
    const int b_rowoff = r7 + ((mat >> 1) << 3);
    const int b_cadd = mat & 1;
    const uint32_t b_roff = (uint32_t)(wN * 64) * 512u + (uint32_t)b_rowoff * 512u;

    for (int c = 0; c < NCHUNK; c++) {
        if (c < 7) {
            copy_img(sb + (((c + 1) & 1) ? SM_B1 : SM_B0), g_wb + (size_t)(c + 1) * 65536, tid);
            CP_COMMIT();
            CP_WAIT1();
        } else {
            CP_WAIT0();
        }
        __syncthreads();

        const uint32_t b_base = sb + ((c & 1) ? SM_B1 : SM_B0) + b_roff;

        float acc[2][8][4];
#pragma unroll
        for (int f = 0; f < 2; f++)
#pragma unroll
            for (int nb = 0; nb < 8; nb++)
#pragma unroll
                for (int j = 0; j < 4; j++) acc[f][nb][j] = 0.f;

#pragma unroll
        for (int ks = 0; ks < 16; ks++) {
            const uint32_t koff = (uint32_t)(((2 * ks + a_cadd) ^ r7) << 4);
            const uint32_t koffb = (uint32_t)(((2 * ks + b_cadd) ^ r7) << 4);
            uint32_t a00, a01, a02, a03, a10, a11, a12, a13;
            ldsm_x4(a00, a01, a02, a03, a_base0 + koff);
            ldsm_x4(a10, a11, a12, a13, a_base1 + koff);
#pragma unroll
            for (int g = 0; g < 4; g++) {
                uint32_t b0, b1, b2, b3;
                ldsm_x4(b0, b1, b2, b3, b_base + (uint32_t)(g * 8192) + koffb);
                mma16816(acc[0][2 * g],     a00, a01, a02, a03, b0, b1);
                mma16816(acc[0][2 * g + 1], a00, a01, a02, a03, b2, b3);
                mma16816(acc[1][2 * g],     a10, a11, a12, a13, b0, b1);
                mma16816(acc[1][2 * g + 1], a10, a11, a12, a13, b2, b3);
            }
        }

        // ---- epilogue: scores, quad-min, GLOBAL runmin update, threshold ----
        const int ncol = 2 * (lane & 3);
        const int code0 = c * 128 + wN * 64 + ncol;
        float lm[2][2];
        lm[0][0] = lm[0][1] = lm[1][0] = lm[1][1] = __int_as_float(0x7f800000);
#pragma unroll
        for (int f = 0; f < 2; f++)
#pragma unroll
            for (int nb = 0; nb < 8; nb++) {
                const float *wq = wsq_s + c * 128 + wN * 64 + nb * 8 + ncol;
                float s;
                s = __fadd_rn(__fmaf_rn(-2.f, acc[f][nb][0], xxv[f][0]), wq[0]); acc[f][nb][0] = s; lm[f][0] = fminf(lm[f][0], s);
                s = __fadd_rn(__fmaf_rn(-2.f, acc[f][nb][1], xxv[f][0]), wq[1]); acc[f][nb][1] = s; lm[f][0] = fminf(lm[f][0], s);
                s = __fadd_rn(__fmaf_rn(-2.f, acc[f][nb][2], xxv[f][1]), wq[0]); acc[f][nb][2] = s; lm[f][1] = fminf(lm[f][1], s);
                s = __fadd_rn(__fmaf_rn(-2.f, acc[f][nb][3], xxv[f][1]), wq[1]); acc[f][nb][3] = s; lm[f][1] = fminf(lm[f][1], s);
            }
#pragma unroll
        for (int o = 1; o <= 2; o <<= 1)
#pragma unroll
            for (int f = 0; f < 2; f++)
#pragma unroll
                for (int r = 0; r < 2; r++)
                    lm[f][r] = fminf(lm[f][r], __shfl_xor_sync(0xffffffffu, lm[f][r], o));
        if ((lane & 3) == 0) {
#pragma unroll
            for (int f = 0; f < 2; f++)
#pragma unroll
                for (int r = 0; r < 2; r++)
                    atomicMin(&run_s[m0 + f * 16 + r * 8 + pr], __float_as_int(lm[f][r]));
        }
        __syncthreads();   // global runmin visible to all warps

#pragma unroll
        for (int f = 0; f < 2; f++)
#pragma unroll
            for (int r = 0; r < 2; r++) {
                const int pxl = m0 + f * 16 + r * 8 + pr;
                const int pix = tile * 128 + pxl;
                const float th = __int_as_float(run_s[pxl]) + THv[f][r];
#pragma unroll
                for (int nb = 0; nb < 8; nb++) {
                    int cb = code0 + nb * 8;
                    float s0 = acc[f][nb][2 * r], s1 = acc[f][nb][2 * r + 1];
                    if (s0 <= th) {
                        int sl = atomicAdd(&cnt_s[pxl], 1);
                        if (sl < 32) g_cand[(size_t)pix * 32 + sl] = cb;
                    }
                    if (s1 <= th) {
                        int sl = atomicAdd(&cnt_s[pxl], 1);
                        if (sl < 32) g_cand[(size_t)pix * 32 + sl] = cb + 1;
                    }
                }
            }
        __syncthreads();
    }

    if (tid < 128) {
        int pix = tile * 128 + tid;
        int cnt = cnt_s[tid];
        g_cnt[pix] = cnt;
        if (cnt == 1) {
            int cidx = g_cand[(size_t)pix * 32];
            g_idx[pix] = cidx;
            out_idxf[pix] = (float)cidx;
        } else {
            int q = atomicAdd(&g_qcnt, 1);
            g_queue[q] = pix;
        }
    }
}

// =====================================================================
// rescore2: warp per queued pixel, one candidate per lane, exact fp32
//   chain (sequential ascending k). x from pixel-major g_xT.
// grid 512 x 256
// =====================================================================
__global__ __launch_bounds__(256) void rescore2(const float *__restrict__ w,
                                                float *__restrict__ out_idxf) {
    const int lane = threadIdx.x & 31;
    const int gwarp = (blockIdx.x * blockDim.x + threadIdx.x) >> 5;
    const int nwarp = (gridDim.x * blockDim.x) >> 5;
    const int total = g_qcnt;
    const float INF = __int_as_float(0x7f800000);

    for (int q = gwarp; q < total; q += nwarp) {
        int pix = g_queue[q];
        int cnt = g_cnt[pix];
        float xxp = g_xx[pix];
        const float4 *xb4 = (const float4 *)(g_xT + (size_t)pix * CDIM);

        float bestd = INF;
        int besti = CODES;
        int nloop = (cnt > 32) ? 32 : 1;   // overflow -> stripe all 1024 codes

        for (int t = 0; t < nloop; t++) {
            int cidx;
            bool active;
            if (cnt > 32) { cidx = t * 32 + lane; active = true; }
            else          { cidx = (lane < cnt) ? g_cand[(size_t)pix * 32 + lane] : 0; active = (lane < cnt); }

            const float4 *wr = (const float4 *)(w + (size_t)cidx * CDIM);
            float dot = 0.f;
#pragma unroll 8
            for (int qq = 0; qq < 64; qq++) {
                float4 wv = wr[qq];
                float4 xv = xb4[qq];
                dot = __fmaf_rn(xv.x, wv.x, dot);
                dot = __fmaf_rn(xv.y, wv.y, dot);
                dot = __fmaf_rn(xv.z, wv.z, dot);
                dot = __fmaf_rn(xv.w, wv.w, dot);
            }
            float d = __fadd_rn(__fmaf_rn(-2.f, dot, xxp), g_wsq[cidx]);
            if (active && (d < bestd || (d == bestd && cidx < besti))) { bestd = d; besti = cidx; }
        }
#pragma unroll
        for (int o = 16; o; o >>= 1) {
            float od = __shfl_xor_sync(0xffffffffu, bestd, o);
            int   oi = __shfl_xor_sync(0xffffffffu, besti, o);
            if (od < bestd || (od == bestd && oi < besti)) { bestd = od; besti = oi; }
        }
        if (lane == 0) {
            g_idx[pix] = besti;
            out_idxf[pix] = (float)besti;
        }
    }
}

// =====================================================================
// gather: quantized = weight[idx], ste = (q - x) + x
// =====================================================================
__global__ __launch_bounds__(256)
void gather_kernel(const float *__restrict__ x, const float *__restrict__ w,
                   float *__restrict__ out) {
    const int b = blockIdx.y;
    const int c0 = blockIdx.x * 32;
    const int hw4 = threadIdx.x * 4;

    int4 rows = *(const int4 *)&g_idx[b * HW + hw4];
    const float *xb = x + (size_t)b * CDIM * HW + hw4;
    float *qo = out + (size_t)b * CDIM * HW + hw4;
    float *so = out + (size_t)NPIX * CDIM + (size_t)b * CDIM * HW + hw4;
    const float *w0 = w + (size_t)rows.x * CDIM;
    const float *w1 = w + (size_t)rows.y * CDIM;
    const float *w2 = w + (size_t)rows.z * CDIM;
    const float *w3 = w + (size_t)rows.w * CDIM;

#pragma unroll 4
    for (int c = c0; c < c0 + 32; c++) {
        float4 qv;
        qv.x = w0[c]; qv.y = w1[c]; qv.z = w2[c]; qv.w = w3[c];
        float4 xv = *(const float4 *)(xb + (size_t)c * HW);
        *(float4 *)(qo + (size_t)c * HW) = qv;
        float4 sv;
        sv.x = __fadd_rn(__fsub_rn(qv.x, xv.x), xv.x);
        sv.y = __fadd_rn(__fsub_rn(qv.y, xv.y), xv.y);
        sv.z = __fadd_rn(__fsub_rn(qv.z, xv.z), xv.z);
        sv.w = __fadd_rn(__fsub_rn(qv.w, xv.w), xv.w);
        *(float4 *)(so + (size_t)c * HW) = sv;
    }
}

// =====================================================================
extern "C" void kernel_launch(void *const *d_in, const int *in_sizes, int n_in,
                              void *d_out, int out_size) {
    const float *x = (const float *)d_in[0];
    const float *w = (const float *)d_in[1];
    if (n_in >= 2 && in_sizes[0] == CODES * CDIM && in_sizes[1] == NPIX * CDIM) {
        const float *tmp = x; x = w; w = tmp;
    }
    float *out = (float *)d_out;
    float *out_idxf = out + 2 * (size_t)NPIX * CDIM;

    cudaFuncSetAttribute(prep_x, cudaFuncAttributeMaxDynamicSharedMemorySize, 128 * XP * 4);
    cudaFuncSetAttribute(mma_kernel, cudaFuncAttributeMaxDynamicSharedMemorySize, SMEM_MMA);

    prep_w<<<128, 256>>>(w);
    prep_x<<<512, 256, 128 * XP * 4>>>(x);
    mma_kernel<<<512, 256, SMEM_MMA>>>(out_idxf);
    rescore2<<<512, 256>>>(w, out_idxf);
    gather_kernel<<<dim3(8, 64), 256>>>(x, w, out);
}

// round 10
// speedup vs baseline: 1.7516x; 1.0577x over previous
#include <cuda_runtime.h>
#include <cuda_fp16.h>
#include <cstdint>

#define CODES 1024
#define CDIM  256
#define HW    1024
#define NPIX  65536
#define NCHUNK 8            // 1024 codes / 128
#define NTILE  512          // 65536 px / 128

// ---------------- static scratch ----------------
__device__ __align__(1024) unsigned char g_wb[NCHUNK * 65536]; // fp16 B images (swizzled)
__device__ __align__(1024) unsigned char g_xb[NTILE * 65536];  // fp16 A images (swizzled)
__device__ __align__(1024) float g_xT[(size_t)NPIX * CDIM];    // fp32 x, pixel-major (64MB)
__device__ float g_wsq[CODES];
__device__ float g_pmax[128];
__device__ float g_xx[NPIX];
__device__ float g_sx[NPIX];
__device__ int   g_cand[NPIX * 32];
__device__ int   g_cnt[NPIX];
__device__ int   g_idx[NPIX];
__device__ int   g_queue[NPIX];
__device__ int   g_qcnt;

// ---------------- helpers ----------------
__device__ __forceinline__ uint32_t smem_u32(const void *p) {
    uint32_t a;
    asm("{ .reg .u64 t; cvta.to.shared.u64 t, %1; cvt.u32.u64 %0, t; }" : "=r"(a) : "l"(p));
    return a;
}
__device__ __forceinline__ void cp16(uint32_t dst, const void *src) {
    asm volatile("cp.async.cg.shared.global [%0], [%1], 16;" :: "r"(dst), "l"(src) : "memory");
}
#define CP_COMMIT() asm volatile("cp.async.commit_group;" ::: "memory")
#define CP_WAIT1()  asm volatile("cp.async.wait_group 1;" ::: "memory")
#define CP_WAIT0()  asm volatile("cp.async.wait_group 0;" ::: "memory")

__device__ __forceinline__ uint32_t packh(float lo, float hi) {
    uint32_t r;
    asm("cvt.rn.f16x2.f32 %0, %1, %2;" : "=r"(r) : "f"(hi), "f"(lo));  // r = hi<<16 | lo
    return r;
}
// image layout: 128 rows x 256 fp16 k-major, rows of 512B = 32 16B-chunks,
// chunk swizzle: stored chunk index = chunk ^ (row & 7)  -> ldmatrix conflict-free
__device__ __forceinline__ uint32_t img_off(int row, int chunk) {
    return (uint32_t)row * 512u + (uint32_t)((chunk ^ (row & 7)) << 4);
}

__device__ __forceinline__ void ldsm_x4(uint32_t &r0, uint32_t &r1, uint32_t &r2, uint32_t &r3,
                                        uint32_t addr) {
    asm volatile("ldmatrix.sync.aligned.m8n8.x4.shared.b16 {%0,%1,%2,%3}, [%4];"
                 : "=r"(r0), "=r"(r1), "=r"(r2), "=r"(r3) : "r"(addr));
}
__device__ __forceinline__ void mma16816(float *d, uint32_t a0, uint32_t a1, uint32_t a2,
                                         uint32_t a3, uint32_t b0, uint32_t b1) {
    asm volatile("mma.sync.aligned.m16n8k16.row.col.f32.f16.f16.f32 "
                 "{%0,%1,%2,%3}, {%4,%5,%6,%7}, {%8,%9}, {%0,%1,%2,%3};"
                 : "+f"(d[0]), "+f"(d[1]), "+f"(d[2]), "+f"(d[3])
                 : "r"(a0), "r"(a1), "r"(a2), "r"(a3), "r"(b0), "r"(b1));
}

// =====================================================================
// prep_w: exact wsq, fp16 swizzled B images, per-block max|w|, zero queue
// grid 128 x 256 (8 codes/block, one warp per code)
// =====================================================================
__global__ void prep_w(const float *__restrict__ w) {
    __shared__ float wm[8];
    if (blockIdx.x == 0 && threadIdx.x == 0) g_qcnt = 0;
    int wid = threadIdx.x >> 5, lane = threadIdx.x & 31;
    int code = blockIdx.x * 8 + wid;
    const float *row = w + code * CDIM;
    float s = 0.f, pm = 0.f;
#pragma unroll
    for (int j = 0; j < 8; j++) {
        float v = row[lane + 32 * j];
        s = __fmaf_rn(v, v, s);
        pm = fmaxf(pm, fabsf(v));
    }
#pragma unroll
    for (int o = 16; o; o >>= 1) {
        s += __shfl_xor_sync(0xffffffffu, s, o);
        pm = fmaxf(pm, __shfl_xor_sync(0xffffffffu, pm, o));
    }
    if (lane == 0) { g_wsq[code] = s; wm[wid] = pm; }
    float f[8];
#pragma unroll
    for (int j = 0; j < 8; j++) f[j] = row[lane * 8 + j];
    uint4 v;
    v.x = packh(f[0], f[1]); v.y = packh(f[2], f[3]);
    v.z = packh(f[4], f[5]); v.w = packh(f[6], f[7]);
    int chunk = code >> 7, lr = code & 127;
    *(uint4 *)(g_wb + chunk * 65536 + img_off(lr, lane)) = v;
    __syncthreads();
    if (threadIdx.x == 0) {
        float m = 0.f;
        for (int i = 0; i < 8; i++) m = fmaxf(m, wm[i]);
        g_pmax[blockIdx.x] = m;
    }
}

// =====================================================================
// prep_x: per 128-pixel tile: transpose+convert x -> fp16 swizzled A image,
//         fp32 pixel-major g_xT, exact sequential xx and sum|x|.
// grid 512 x 256.
// =====================================================================
#define XP 130
__global__ __launch_bounds__(256) void prep_x(const float *__restrict__ x) {
    extern __shared__ float sm[];
    const int tile = blockIdx.x;
    const int b = tile >> 3, hw0 = (tile & 7) * 128;
    const int tid = threadIdx.x;
    unsigned char *dst = g_xb + (size_t)tile * 65536;
    float *xtd = g_xT + (size_t)tile * 128 * CDIM;
    float xxa = 0.f, sxa = 0.f;

    for (int h = 0; h < 2; h++) {
        const float *src = x + (size_t)b * CDIM * HW + (size_t)(h * 128) * HW + hw0;
#pragma unroll
        for (int it = 0; it < 64; it++) {
            int idx = tid + 256 * it;
            int kk = idx >> 7, p = idx & 127;
            sm[kk * XP + p] = src[(size_t)kk * HW + p];
        }
        __syncthreads();
        if (tid < 128) {
            for (int kk = 0; kk < 128; kk++) {
                float v = sm[kk * XP + tid];
                xxa = __fadd_rn(xxa, __fmul_rn(v, v));
                sxa = __fadd_rn(sxa, fabsf(v));
            }
        }
        // fp32 transpose out: g_xT[pix][h*128 + k]
        {
            int k4 = tid & 31;
            for (int pp = tid >> 5; pp < 128; pp += 8) {
                float4 v4;
                v4.x = sm[(k4 * 4 + 0) * XP + pp];
                v4.y = sm[(k4 * 4 + 1) * XP + pp];
                v4.z = sm[(k4 * 4 + 2) * XP + pp];
                v4.w = sm[(k4 * 4 + 3) * XP + pp];
                *(float4 *)(xtd + (size_t)pp * CDIM + h * 128 + k4 * 4) = v4;
            }
        }
        // fp16 swizzled A image
        int p = tid & 127;
#pragma unroll
        for (int it = 0; it < 8; it++) {
            int oct = (tid >> 7) * 8 + it;
            float f[8];
#pragma unroll
            for (int j = 0; j < 8; j++) f[j] = sm[(oct * 8 + j) * XP + p];
            uint4 v;
            v.x = packh(f[0], f[1]); v.y = packh(f[2], f[3]);
            v.z = packh(f[4], f[5]); v.w = packh(f[6], f[7]);
            *(uint4 *)(dst + img_off(p, h * 16 + oct)) = v;
        }
        __syncthreads();
    }
    if (tid < 128) {
        g_xx[tile * 128 + tid] = xxa;
        g_sx[tile * 128 + tid] = sxa;
    }
}

// =====================================================================
// mma_kernel: warp tiling 4(px-groups of 32) x 2(N-halves of 64 codes).
//   Per ks: 2 A-LDSM + 4 B-LDSM + 16 MMA. Double-buffered B.
//   Pixel-GLOBAL runmin shared across warps via smem atomicMin.
// grid 512 x 256
// =====================================================================
#define SM_WSQ 0
#define SM_CNT 4096
#define SM_RUN 5120
#define SM_A   8192
#define SM_B0  73728
#define SM_B1  139264
#define SMEM_MMA 204800

__device__ __forceinline__ void copy_img(uint32_t dst, const unsigned char *src, int tid) {
#pragma unroll
    for (int i = 0; i < 16; i++) {
        int c = tid + 256 * i;        // 4096 chunks of 16B
        cp16(dst + (uint32_t)c * 16u, src + (size_t)c * 16u);
    }
}

__global__ __launch_bounds__(256, 1) void mma_kernel(float *__restrict__ out_idxf) {
    extern __shared__ char smc[];
    uint32_t sb = smem_u32(smc);
    float *wsq_s = (float *)(smc + SM_WSQ);
    int *cnt_s = (int *)(smc + SM_CNT);
    int *run_s = (int *)(smc + SM_RUN);
    const int tid = threadIdx.x, warp = tid >> 5, lane = tid & 31;
    const int tile = blockIdx.x;
    const int wM = warp & 3;        // pixel group: 32 px
    const int wN = warp >> 2;       // code half: 64 codes
    const int m0 = wM * 32;

    copy_img(sb + SM_A, g_xb + (size_t)tile * 65536, tid);
    copy_img(sb + SM_B0, g_wb, tid);
    CP_COMMIT();

    for (int i = tid; i < CODES; i += 256) wsq_s[i] = g_wsq[i];
    if (tid < 128) {
        cnt_s[tid] = 0;
        run_s[tid] = 0x7f800000;           // +inf
    }
    if (tid == 0) {
        float m = 0.f;
        for (int i = 0; i < 128; i++) m = fmaxf(m, g_pmax[i]);
        ((float *)(smc + SM_CNT))[130] = m;
    }
    __syncthreads();
    const float wmax = ((float *)(smc + SM_CNT))[130];

    // 4 pixel rows per thread: [f][r] = m0 + f*16 + r*8 + (lane>>2)
    const int pr = lane >> 2;
    float xxv[2][2], THv[2][2];
#pragma unroll
    for (int f = 0; f < 2; f++)
#pragma unroll
        for (int r = 0; r < 2; r++) {
            int pix = tile * 128 + m0 + f * 16 + r * 8 + pr;
            xxv[f][r] = g_xx[pix];
            THv[f][r] = __fmaf_rn(g_sx[pix] * wmax, 0.006f, 4e-4f);   // fp16 bound, 1.5x safety
        }

    // ldmatrix addressing
    const int mat = lane >> 3, r7 = lane & 7;
    const int a_row0 = m0 + r7 + ((mat & 1) << 3);
    const int a_cadd = mat >> 1;
    const uint32_t a_base0 = sb + SM_A + (uint32_t)a_row0 * 512u;       // f=0
    const uint32_t a_base1 = a_base0 + 16u * 512u;                      // f=1
    const int b_rowoff = r7 + ((mat >> 1) << 3);
    const int b_cadd = mat & 1;
    const uint32_t b_roff = (uint32_t)(wN * 64) * 512u + (uint32_t)b_rowoff * 512u;

    for (int c = 0; c < NCHUNK; c++) {
        if (c < 7) {
            copy_img(sb + (((c + 1) & 1) ? SM_B1 : SM_B0), g_wb + (size_t)(c + 1) * 65536, tid);
            CP_COMMIT();
            CP_WAIT1();
        } else {
            CP_WAIT0();
        }
        __syncthreads();

        const uint32_t b_base = sb + ((c & 1) ? SM_B1 : SM_B0) + b_roff;

        float acc[2][8][4];
#pragma unroll
        for (int f = 0; f < 2; f++)
#pragma unroll
            for (int nb = 0; nb < 8; nb++)
#pragma unroll
                for (int j = 0; j < 4; j++) acc[f][nb][j] = 0.f;

#pragma unroll
        for (int ks = 0; ks < 16; ks++) {
            const uint32_t koff = (uint32_t)(((2 * ks + a_cadd) ^ r7) << 4);
            const uint32_t koffb = (uint32_t)(((2 * ks + b_cadd) ^ r7) << 4);
            uint32_t a00, a01, a02, a03, a10, a11, a12, a13;
            ldsm_x4(a00, a01, a02, a03, a_base0 + koff);
            ldsm_x4(a10, a11, a12, a13, a_base1 + koff);
#pragma unroll
            for (int g = 0; g < 4; g++) {
                uint32_t b0, b1, b2, b3;
                ldsm_x4(b0, b1, b2, b3, b_base + (uint32_t)(g * 8192) + koffb);
                mma16816(acc[0][2 * g],     a00, a01, a02, a03, b0, b1);
                mma16816(acc[0][2 * g + 1], a00, a01, a02, a03, b2, b3);
                mma16816(acc[1][2 * g],     a10, a11, a12, a13, b0, b1);
                mma16816(acc[1][2 * g + 1], a10, a11, a12, a13, b2, b3);
            }
        }

        // ---- epilogue: scores, quad-min, GLOBAL runmin update, threshold ----
        const int ncol = 2 * (lane & 3);
        const int code0 = c * 128 + wN * 64 + ncol;
        float lm[2][2];
        lm[0][0] = lm[0][1] = lm[1][0] = lm[1][1] = __int_as_float(0x7f800000);
#pragma unroll
        for (int f = 0; f < 2; f++)
#pragma unroll
            for (int nb = 0; nb < 8; nb++) {
                const float *wq = wsq_s + c * 128 + wN * 64 + nb * 8 + ncol;
                float s;
                s = __fadd_rn(__fmaf_rn(-2.f, acc[f][nb][0], xxv[f][0]), wq[0]); acc[f][nb][0] = s; lm[f][0] = fminf(lm[f][0], s);
                s = __fadd_rn(__fmaf_rn(-2.f, acc[f][nb][1], xxv[f][0]), wq[1]); acc[f][nb][1] = s; lm[f][0] = fminf(lm[f][0], s);
                s = __fadd_rn(__fmaf_rn(-2.f, acc[f][nb][2], xxv[f][1]), wq[0]); acc[f][nb][2] = s; lm[f][1] = fminf(lm[f][1], s);
                s = __fadd_rn(__fmaf_rn(-2.f, acc[f][nb][3], xxv[f][1]), wq[1]); acc[f][nb][3] = s; lm[f][1] = fminf(lm[f][1], s);
            }
#pragma unroll
        for (int o = 1; o <= 2; o <<= 1)
#pragma unroll
            for (int f = 0; f < 2; f++)
#pragma unroll
                for (int r = 0; r < 2; r++)
                    lm[f][r] = fminf(lm[f][r], __shfl_xor_sync(0xffffffffu, lm[f][r], o));
        if ((lane & 3) == 0) {
#pragma unroll
            for (int f = 0; f < 2; f++)
#pragma unroll
                for (int r = 0; r < 2; r++)
                    atomicMin(&run_s[m0 + f * 16 + r * 8 + pr], __float_as_int(lm[f][r]));
        }
        __syncthreads();   // global runmin visible to all warps

#pragma unroll
        for (int f = 0; f < 2; f++)
#pragma unroll
            for (int r = 0; r < 2; r++) {
                const int pxl = m0 + f * 16 + r * 8 + pr;
                const int pix = tile * 128 + pxl;
                const float th = __int_as_float(run_s[pxl]) + THv[f][r];
#pragma unroll
                for (int nb = 0; nb < 8; nb++) {
                    int cb = code0 + nb * 8;
                    float s0 = acc[f][nb][2 * r], s1 = acc[f][nb][2 * r + 1];
                    if (s0 <= th) {
                        int sl = atomicAdd(&cnt_s[pxl], 1);
                        if (sl < 32) g_cand[(size_t)pix * 32 + sl] = cb;
                    }
                    if (s1 <= th) {
                        int sl = atomicAdd(&cnt_s[pxl], 1);
                        if (sl < 32) g_cand[(size_t)pix * 32 + sl] = cb + 1;
                    }
                }
            }
        __syncthreads();
    }

    if (tid < 128) {
        int pix = tile * 128 + tid;
        int cnt = cnt_s[tid];
        g_cnt[pix] = cnt;
        if (cnt == 1) {
            int cidx = g_cand[(size_t)pix * 32];
            g_idx[pix] = cidx;
            out_idxf[pix] = (float)cidx;
        } else {
            int q = atomicAdd(&g_qcnt, 1);
            g_queue[q] = pix;
        }
    }
}

// =====================================================================
// rescore2: warp per queued pixel, one candidate per lane, exact fp32
//   chain (sequential ascending k). x from pixel-major g_xT.
//   Dot loop PREDICATED on active -> L1 traffic scales with cnt, not 32.
// grid 512 x 256
// =====================================================================
__global__ __launch_bounds__(256) void rescore2(const float *__restrict__ w,
                                                float *__restrict__ out_idxf) {
    const int lane = threadIdx.x & 31;
    const int gwarp = (blockIdx.x * blockDim.x + threadIdx.x) >> 5;
    const int nwarp = (gridDim.x * blockDim.x) >> 5;
    const int total = g_qcnt;
    const float INF = __int_as_float(0x7f800000);

    for (int q = gwarp; q < total; q += nwarp) {
        int pix = g_queue[q];
        int cnt = g_cnt[pix];
        float xxp = g_xx[pix];
        const float4 *xb4 = (const float4 *)(g_xT + (size_t)pix * CDIM);

        float bestd = INF;
        int besti = CODES;
        int nloop = (cnt > 32) ? 32 : 1;   // overflow -> stripe all 1024 codes

        for (int t = 0; t < nloop; t++) {
            int cidx;
            bool active;
            if (cnt > 32) { cidx = t * 32 + lane; active = true; }
            else          { cidx = (lane < cnt) ? g_cand[(size_t)pix * 32 + lane] : 0; active = (lane < cnt); }

            if (active) {
                const float4 *wr = (const float4 *)(w + (size_t)cidx * CDIM);
                float dot = 0.f;
#pragma unroll 8
                for (int qq = 0; qq < 64; qq++) {
                    float4 wv = wr[qq];
                    float4 xv = xb4[qq];
                    dot = __fmaf_rn(xv.x, wv.x, dot);
                    dot = __fmaf_rn(xv.y, wv.y, dot);
                    dot = __fmaf_rn(xv.z, wv.z, dot);
                    dot = __fmaf_rn(xv.w, wv.w, dot);
                }
                float d = __fadd_rn(__fmaf_rn(-2.f, dot, xxp), g_wsq[cidx]);
                if (d < bestd || (d == bestd && cidx < besti)) { bestd = d; besti = cidx; }
            }
        }
#pragma unroll
        for (int o = 16; o; o >>= 1) {
            float od = __shfl_xor_sync(0xffffffffu, bestd, o);
            int   oi = __shfl_xor_sync(0xffffffffu, besti, o);
            if (od < bestd || (od == bestd && oi < besti)) { bestd = od; besti = oi; }
        }
        if (lane == 0) {
            g_idx[pix] = besti;
            out_idxf[pix] = (float)besti;
        }
    }
}

// =====================================================================
// gather: quantized = weight[idx], ste = (q - x) + x
// =====================================================================
__global__ __launch_bounds__(256)
void gather_kernel(const float *__restrict__ x, const float *__restrict__ w,
                   float *__restrict__ out) {
    const int b = blockIdx.y;
    const int c0 = blockIdx.x * 32;
    const int hw4 = threadIdx.x * 4;

    int4 rows = *(const int4 *)&g_idx[b * HW + hw4];
    const float *xb = x + (size_t)b * CDIM * HW + hw4;
    float *qo = out + (size_t)b * CDIM * HW + hw4;
    float *so = out + (size_t)NPIX * CDIM + (size_t)b * CDIM * HW + hw4;
    const float *w0 = w + (size_t)rows.x * CDIM;
    const float *w1 = w + (size_t)rows.y * CDIM;
    const float *w2 = w + (size_t)rows.z * CDIM;
    const float *w3 = w + (size_t)rows.w * CDIM;

#pragma unroll 4
    for (int c = c0; c < c0 + 32; c++) {
        float4 qv;
        qv.x = w0[c]; qv.y = w1[c]; qv.z = w2[c]; qv.w = w3[c];
        float4 xv = *(const float4 *)(xb + (size_t)c * HW);
        *(float4 *)(qo + (size_t)c * HW) = qv;
        float4 sv;
        sv.x = __fadd_rn(__fsub_rn(qv.x, xv.x), xv.x);
        sv.y = __fadd_rn(__fsub_rn(qv.y, xv.y), xv.y);
        sv.z = __fadd_rn(__fsub_rn(qv.z, xv.z), xv.z);
        sv.w = __fadd_rn(__fsub_rn(qv.w, xv.w), xv.w);
        *(float4 *)(so + (size_t)c * HW) = sv;
    }
}

// =====================================================================
extern "C" void kernel_launch(void *const *d_in, const int *in_sizes, int n_in,
                              void *d_out, int out_size) {
    const float *x = (const float *)d_in[0];
    const float *w = (const float *)d_in[1];
    if (n_in >= 2 && in_sizes[0] == CODES * CDIM && in_sizes[1] == NPIX * CDIM) {
        const float *tmp = x; x = w; w = tmp;
    }
    float *out = (float *)d_out;
    float *out_idxf = out + 2 * (size_t)NPIX * CDIM;

    cudaFuncSetAttribute(prep_x, cudaFuncAttributeMaxDynamicSharedMemorySize, 128 * XP * 4);
    cudaFuncSetAttribute(mma_kernel, cudaFuncAttributeMaxDynamicSharedMemorySize, SMEM_MMA);

    prep_w<<<128, 256>>>(w);
    prep_x<<<512, 256, 128 * XP * 4>>>(x);
    mma_kernel<<<512, 256, SMEM_MMA>>>(out_idxf);
    rescore2<<<512, 256>>>(w, out_idxf);
    gather_kernel<<<dim3(8, 64), 256>>>(x, w, out);
}

// round 11
// speedup vs baseline: 2.1443x; 1.2242x over previous
#include <cuda_runtime.h>
#include <cuda_fp16.h>
#include <cstdint>

#define CODES 1024
#define CDIM  256
#define HW    1024
#define NPIX  65536
#define NCHUNK 8            // 1024 codes / 128
#define NTILE  512          // 65536 px / 128

// ---------------- static scratch ----------------
__device__ __align__(1024) unsigned char g_wb[NCHUNK * 65536]; // fp16 B images (swizzled)
__device__ __align__(1024) unsigned char g_xb[NTILE * 65536];  // fp16 A images (swizzled)
__device__ __align__(1024) float g_xT[(size_t)NPIX * CDIM];    // fp32 x, pixel-major (64MB)
__device__ float g_wsq[CODES];
__device__ float g_pmax[128];
__device__ float g_xx[NPIX];
__device__ float g_sx[NPIX];
__device__ int   g_cand[NPIX * 32];
__device__ float g_cs[NPIX * 32];      // approx score per candidate
__device__ int   g_cnt[NPIX];
__device__ int   g_idx[NPIX];
__device__ int   g_queue[NPIX];
__device__ int   g_qcnt;

// ---------------- helpers ----------------
__device__ __forceinline__ uint32_t smem_u32(const void *p) {
    uint32_t a;
    asm("{ .reg .u64 t; cvta.to.shared.u64 t, %1; cvt.u32.u64 %0, t; }" : "=r"(a) : "l"(p));
    return a;
}
__device__ __forceinline__ void cp16(uint32_t dst, const void *src) {
    asm volatile("cp.async.cg.shared.global [%0], [%1], 16;" :: "r"(dst), "l"(src) : "memory");
}
#define CP_COMMIT() asm volatile("cp.async.commit_group;" ::: "memory")
#define CP_WAIT1()  asm volatile("cp.async.wait_group 1;" ::: "memory")
#define CP_WAIT0()  asm volatile("cp.async.wait_group 0;" ::: "memory")

__device__ __forceinline__ uint32_t packh(float lo, float hi) {
    uint32_t r;
    asm("cvt.rn.f16x2.f32 %0, %1, %2;" : "=r"(r) : "f"(hi), "f"(lo));  // r = hi<<16 | lo
    return r;
}
// image layout: 128 rows x 256 fp16 k-major, rows of 512B = 32 16B-chunks,
// chunk swizzle: stored chunk index = chunk ^ (row & 7)  -> ldmatrix conflict-free
__device__ __forceinline__ uint32_t img_off(int row, int chunk) {
    return (uint32_t)row * 512u + (uint32_t)((chunk ^ (row & 7)) << 4);
}

__device__ __forceinline__ void ldsm_x4(uint32_t &r0, uint32_t &r1, uint32_t &r2, uint32_t &r3,
                                        uint32_t addr) {
    asm volatile("ldmatrix.sync.aligned.m8n8.x4.shared.b16 {%0,%1,%2,%3}, [%4];"
                 : "=r"(r0), "=r"(r1), "=r"(r2), "=r"(r3) : "r"(addr));
}
__device__ __forceinline__ void mma16816(float *d, uint32_t a0, uint32_t a1, uint32_t a2,
                                         uint32_t a3, uint32_t b0, uint32_t b1) {
    asm volatile("mma.sync.aligned.m16n8k16.row.col.f32.f16.f16.f32 "
                 "{%0,%1,%2,%3}, {%4,%5,%6,%7}, {%8,%9}, {%0,%1,%2,%3};"
                 : "+f"(d[0]), "+f"(d[1]), "+f"(d[2]), "+f"(d[3])
                 : "r"(a0), "r"(a1), "r"(a2), "r"(a3), "r"(b0), "r"(b1));
}

// =====================================================================
// prep_w: exact wsq, fp16 swizzled B images, per-block max|w|, zero queue
// grid 128 x 256 (8 codes/block, one warp per code)
// =====================================================================
__global__ void prep_w(const float *__restrict__ w) {
    __shared__ float wm[8];
    if (blockIdx.x == 0 && threadIdx.x == 0) g_qcnt = 0;
    int wid = threadIdx.x >> 5, lane = threadIdx.x & 31;
    int code = blockIdx.x * 8 + wid;
    const float *row = w + code * CDIM;
    float s = 0.f, pm = 0.f;
#pragma unroll
    for (int j = 0; j < 8; j++) {
        float v = row[lane + 32 * j];
        s = __fmaf_rn(v, v, s);
        pm = fmaxf(pm, fabsf(v));
    }
#pragma unroll
    for (int o = 16; o; o >>= 1) {
        s += __shfl_xor_sync(0xffffffffu, s, o);
        pm = fmaxf(pm, __shfl_xor_sync(0xffffffffu, pm, o));
    }
    if (lane == 0) { g_wsq[code] = s; wm[wid] = pm; }
    float f[8];
#pragma unroll
    for (int j = 0; j < 8; j++) f[j] = row[lane * 8 + j];
    uint4 v;
    v.x = packh(f[0], f[1]); v.y = packh(f[2], f[3]);
    v.z = packh(f[4], f[5]); v.w = packh(f[6], f[7]);
    int chunk = code >> 7, lr = code & 127;
    *(uint4 *)(g_wb + chunk * 65536 + img_off(lr, lane)) = v;
    __syncthreads();
    if (threadIdx.x == 0) {
        float m = 0.f;
        for (int i = 0; i < 8; i++) m = fmaxf(m, wm[i]);
        g_pmax[blockIdx.x] = m;
    }
}

// =====================================================================
// prep_x: per 128-pixel tile: transpose+convert x -> fp16 swizzled A image,
//         fp32 pixel-major g_xT, exact sequential xx and sum|x|.
// grid 512 x 256.
// =====================================================================
#define XP 130
__global__ __launch_bounds__(256) void prep_x(const float *__restrict__ x) {
    extern __shared__ float sm[];
    const int tile = blockIdx.x;
    const int b = tile >> 3, hw0 = (tile & 7) * 128;
    const int tid = threadIdx.x;
    unsigned char *dst = g_xb + (size_t)tile * 65536;
    float *xtd = g_xT + (size_t)tile * 128 * CDIM;
    float xxa = 0.f, sxa = 0.f;

    for (int h = 0; h < 2; h++) {
        const float *src = x + (size_t)b * CDIM * HW + (size_t)(h * 128) * HW + hw0;
#pragma unroll
        for (int it = 0; it < 64; it++) {
            int idx = tid + 256 * it;
            int kk = idx >> 7, p = idx & 127;
            sm[kk * XP + p] = src[(size_t)kk * HW + p];
        }
        __syncthreads();
        if (tid < 128) {
            for (int kk = 0; kk < 128; kk++) {
                float v = sm[kk * XP + tid];
                xxa = __fadd_rn(xxa, __fmul_rn(v, v));
                sxa = __fadd_rn(sxa, fabsf(v));
            }
        }
        // fp32 transpose out: g_xT[pix][h*128 + k]
        {
            int k4 = tid & 31;
            for (int pp = tid >> 5; pp < 128; pp += 8) {
                float4 v4;
                v4.x = sm[(k4 * 4 + 0) * XP + pp];
                v4.y = sm[(k4 * 4 + 1) * XP + pp];
                v4.z = sm[(k4 * 4 + 2) * XP + pp];
                v4.w = sm[(k4 * 4 + 3) * XP + pp];
                *(float4 *)(xtd + (size_t)pp * CDIM + h * 128 + k4 * 4) = v4;
            }
        }
        // fp16 swizzled A image
        int p = tid & 127;
#pragma unroll
        for (int it = 0; it < 8; it++) {
            int oct = (tid >> 7) * 8 + it;
            float f[8];
#pragma unroll
            for (int j = 0; j < 8; j++) f[j] = sm[(oct * 8 + j) * XP + p];
            uint4 v;
            v.x = packh(f[0], f[1]); v.y = packh(f[2], f[3]);
            v.z = packh(f[4], f[5]); v.w = packh(f[6], f[7]);
            *(uint4 *)(dst + img_off(p, h * 16 + oct)) = v;
        }
        __syncthreads();
    }
    if (tid < 128) {
        g_xx[tile * 128 + tid] = xxa;
        g_sx[tile * 128 + tid] = sxa;
    }
}

// =====================================================================
// mma_kernel: warp tiling 4(px-groups of 32) x 2(N-halves of 64 codes).
//   Per ks: 2 A-LDSM + 4 B-LDSM + 16 MMA. Double-buffered B.
//   Pixel-GLOBAL runmin via smem atomicMin. Candidates stored WITH scores;
//   tail refilters against the FINAL min -> tiny queue.
// grid 512 x 256
// =====================================================================
#define SM_WSQ 0
#define SM_CNT 4096
#define SM_RUN 5120
#define SM_A   8192
#define SM_B0  73728
#define SM_B1  139264
#define SMEM_MMA 204800

__device__ __forceinline__ void copy_img(uint32_t dst, const unsigned char *src, int tid) {
#pragma unroll
    for (int i = 0; i < 16; i++) {
        int c = tid + 256 * i;        // 4096 chunks of 16B
        cp16(dst + (uint32_t)c * 16u, src + (size_t)c * 16u);
    }
}

__global__ __launch_bounds__(256, 1) void mma_kernel(float *__restrict__ out_idxf) {
    extern __shared__ char smc[];
    uint32_t sb = smem_u32(smc);
    float *wsq_s = (float *)(smc + SM_WSQ);
    int *cnt_s = (int *)(smc + SM_CNT);
    int *run_s = (int *)(smc + SM_RUN);
    const int tid = threadIdx.x, warp = tid >> 5, lane = tid & 31;
    const int tile = blockIdx.x;
    const int wM = warp & 3;        // pixel group: 32 px
    const int wN = warp >> 2;       // code half: 64 codes
    const int m0 = wM * 32;

    copy_img(sb + SM_A, g_xb + (size_t)tile * 65536, tid);
    copy_img(sb + SM_B0, g_wb, tid);
    CP_COMMIT();

    for (int i = tid; i < CODES; i += 256) wsq_s[i] = g_wsq[i];
    if (tid < 128) {
        cnt_s[tid] = 0;
        run_s[tid] = 0x7f800000;           // +inf
    }
    if (tid == 0) {
        float m = 0.f;
        for (int i = 0; i < 128; i++) m = fmaxf(m, g_pmax[i]);
        ((float *)(smc + SM_CNT))[130] = m;
    }
    __syncthreads();
    const float wmax = ((float *)(smc + SM_CNT))[130];

    // 4 pixel rows per thread: [f][r] = m0 + f*16 + r*8 + (lane>>2)
    const int pr = lane >> 2;
    float xxv[2][2], THv[2][2];
#pragma unroll
    for (int f = 0; f < 2; f++)
#pragma unroll
        for (int r = 0; r < 2; r++) {
            int pix = tile * 128 + m0 + f * 16 + r * 8 + pr;
            xxv[f][r] = g_xx[pix];
            THv[f][r] = __fmaf_rn(g_sx[pix] * wmax, 0.006f, 4e-4f);   // fp16 bound, 1.5x safety
        }

    // ldmatrix addressing
    const int mat = lane >> 3, r7 = lane & 7;
    const int a_row0 = m0 + r7 + ((mat & 1) << 3);
    const int a_cadd = mat >> 1;
    const uint32_t a_base0 = sb + SM_A + (uint32_t)a_row0 * 512u;       // f=0
    const uint32_t a_base1 = a_base0 + 16u * 512u;                      // f=1
    const int b_rowoff = r7 + ((mat >> 1) << 3);
    const int b_cadd = mat & 1;
    const uint32_t b_roff = (uint32_t)(wN * 64) * 512u + (uint32_t)b_rowoff * 512u;

    for (int c = 0; c < NCHUNK; c++) {
        if (c < 7) {
            copy_img(sb + (((c + 1) & 1) ? SM_B1 : SM_B0), g_wb + (size_t)(c + 1) * 65536, tid);
            CP_COMMIT();
            CP_WAIT1();
        } else {
            CP_WAIT0();
        }
        __syncthreads();

        const uint32_t b_base = sb + ((c & 1) ? SM_B1 : SM_B0) + b_roff;

        float acc[2][8][4];
#pragma unroll
        for (int f = 0; f < 2; f++)
#pragma unroll
            for (int nb = 0; nb < 8; nb++)
#pragma unroll
                for (int j = 0; j < 4; j++) acc[f][nb][j] = 0.f;

#pragma unroll
        for (int ks = 0; ks < 16; ks++) {
            const uint32_t koff = (uint32_t)(((2 * ks + a_cadd) ^ r7) << 4);
            const uint32_t koffb = (uint32_t)(((2 * ks + b_cadd) ^ r7) << 4);
            uint32_t a00, a01, a02, a03, a10, a11, a12, a13;
            ldsm_x4(a00, a01, a02, a03, a_base0 + koff);
            ldsm_x4(a10, a11, a12, a13, a_base1 + koff);
#pragma unroll
            for (int g = 0; g < 4; g++) {
                uint32_t b0, b1, b2, b3;
                ldsm_x4(b0, b1, b2, b3, b_base + (uint32_t)(g * 8192) + koffb);
                mma16816(acc[0][2 * g],     a00, a01, a02, a03, b0, b1);
                mma16816(acc[0][2 * g + 1], a00, a01, a02, a03, b2, b3);
                mma16816(acc[1][2 * g],     a10, a11, a12, a13, b0, b1);
                mma16816(acc[1][2 * g + 1], a10, a11, a12, a13, b2, b3);
            }
        }

        // ---- epilogue: scores, quad-min, GLOBAL runmin update, threshold ----
        const int ncol = 2 * (lane & 3);
        const int code0 = c * 128 + wN * 64 + ncol;
        float lm[2][2];
        lm[0][0] = lm[0][1] = lm[1][0] = lm[1][1] = __int_as_float(0x7f800000);
#pragma unroll
        for (int f = 0; f < 2; f++)
#pragma unroll
            for (int nb = 0; nb < 8; nb++) {
                const float *wq = wsq_s + c * 128 + wN * 64 + nb * 8 + ncol;
                float s;
                s = __fadd_rn(__fmaf_rn(-2.f, acc[f][nb][0], xxv[f][0]), wq[0]); acc[f][nb][0] = s; lm[f][0] = fminf(lm[f][0], s);
                s = __fadd_rn(__fmaf_rn(-2.f, acc[f][nb][1], xxv[f][0]), wq[1]); acc[f][nb][1] = s; lm[f][0] = fminf(lm[f][0], s);
                s = __fadd_rn(__fmaf_rn(-2.f, acc[f][nb][2], xxv[f][1]), wq[0]); acc[f][nb][2] = s; lm[f][1] = fminf(lm[f][1], s);
                s = __fadd_rn(__fmaf_rn(-2.f, acc[f][nb][3], xxv[f][1]), wq[1]); acc[f][nb][3] = s; lm[f][1] = fminf(lm[f][1], s);
            }
#pragma unroll
        for (int o = 1; o <= 2; o <<= 1)
#pragma unroll
            for (int f = 0; f < 2; f++)
#pragma unroll
                for (int r = 0; r < 2; r++)
                    lm[f][r] = fminf(lm[f][r], __shfl_xor_sync(0xffffffffu, lm[f][r], o));
        if ((lane & 3) == 0) {
#pragma unroll
            for (int f = 0; f < 2; f++)
#pragma unroll
                for (int r = 0; r < 2; r++)
                    atomicMin(&run_s[m0 + f * 16 + r * 8 + pr], __float_as_int(lm[f][r]));
        }
        __syncthreads();   // global runmin visible to all warps

#pragma unroll
        for (int f = 0; f < 2; f++)
#pragma unroll
            for (int r = 0; r < 2; r++) {
                const int pxl = m0 + f * 16 + r * 8 + pr;
                const int pix = tile * 128 + pxl;
                const float th = __int_as_float(run_s[pxl]) + THv[f][r];
#pragma unroll
                for (int nb = 0; nb < 8; nb++) {
                    int cb = code0 + nb * 8;
                    float s0 = acc[f][nb][2 * r], s1 = acc[f][nb][2 * r + 1];
                    if (s0 <= th) {
                        int sl = atomicAdd(&cnt_s[pxl], 1);
                        if (sl < 32) {
                            g_cand[(size_t)pix * 32 + sl] = cb;
                            g_cs[(size_t)pix * 32 + sl] = s0;
                        }
                    }
                    if (s1 <= th) {
                        int sl = atomicAdd(&cnt_s[pxl], 1);
                        if (sl < 32) {
                            g_cand[(size_t)pix * 32 + sl] = cb + 1;
                            g_cs[(size_t)pix * 32 + sl] = s1;
                        }
                    }
                }
            }
        __syncthreads();
    }

    // ---- tail: refilter candidates against FINAL runmin, finalize or queue ----
    if (tid < 128) {
        int pix = tile * 128 + tid;
        int cnt = cnt_s[tid];
        if (cnt > 32) {
            g_cnt[pix] = cnt;                       // overflow -> full-scan path
            int q = atomicAdd(&g_qcnt, 1);
            g_queue[q] = pix;
        } else {
            const float th = __int_as_float(run_s[tid]) +
                             __fmaf_rn(g_sx[pix] * wmax, 0.006f, 4e-4f);
            int nk = 0, first = 0;
            for (int j = 0; j < cnt; j++) {
                int code = g_cand[(size_t)pix * 32 + j];
                float s = g_cs[(size_t)pix * 32 + j];
                if (s <= th) {
                    g_cand[(size_t)pix * 32 + nk] = code;   // in-place compact (nk<=j)
                    if (nk == 0) first = code;
                    nk++;
                }
            }
            g_cnt[pix] = nk;
            if (nk == 1) {
                g_idx[pix] = first;
                out_idxf[pix] = (float)first;
            } else {
                int q = atomicAdd(&g_qcnt, 1);
                g_queue[q] = pix;
            }
        }
    }
}

// =====================================================================
// rescore2: warp per queued pixel, one candidate per lane, exact fp32
//   chain (sequential ascending k). x from pixel-major g_xT.
// grid 512 x 256
// =====================================================================
__global__ __launch_bounds__(256) void rescore2(const float *__restrict__ w,
                                                float *__restrict__ out_idxf) {
    const int lane = threadIdx.x & 31;
    const int gwarp = (blockIdx.x * blockDim.x + threadIdx.x) >> 5;
    const int nwarp = (gridDim.x * blockDim.x) >> 5;
    const int total = g_qcnt;
    const float INF = __int_as_float(0x7f800000);

    for (int q = gwarp; q < total; q += nwarp) {
        int pix = g_queue[q];
        int cnt = g_cnt[pix];
        float xxp = g_xx[pix];
        const float4 *xb4 = (const float4 *)(g_xT + (size_t)pix * CDIM);

        float bestd = INF;
        int besti = CODES;
        int nloop = (cnt > 32) ? 32 : 1;   // overflow -> stripe all 1024 codes

        for (int t = 0; t < nloop; t++) {
            int cidx;
            bool active;
            if (cnt > 32) { cidx = t * 32 + lane; active = true; }
            else          { cidx = (lane < cnt) ? g_cand[(size_t)pix * 32 + lane] : 0; active = (lane < cnt); }

            if (active) {
                const float4 *wr = (const float4 *)(w + (size_t)cidx * CDIM);
                float dot = 0.f;
#pragma unroll 8
                for (int qq = 0; qq < 64; qq++) {
                    float4 wv = wr[qq];
                    float4 xv = xb4[qq];
                    dot = __fmaf_rn(xv.x, wv.x, dot);
                    dot = __fmaf_rn(xv.y, wv.y, dot);
                    dot = __fmaf_rn(xv.z, wv.z, dot);
                    dot = __fmaf_rn(xv.w, wv.w, dot);
                }
                float d = __fadd_rn(__fmaf_rn(-2.f, dot, xxp), g_wsq[cidx]);
                if (d < bestd || (d == bestd && cidx < besti)) { bestd = d; besti = cidx; }
            }
        }
#pragma unroll
        for (int o = 16; o; o >>= 1) {
            float od = __shfl_xor_sync(0xffffffffu, bestd, o);
            int   oi = __shfl_xor_sync(0xffffffffu, besti, o);
            if (od < bestd || (od == bestd && oi < besti)) { bestd = od; besti = oi; }
        }
        if (lane == 0) {
            g_idx[pix] = besti;
            out_idxf[pix] = (float)besti;
        }
    }
}

// =====================================================================
// gather: quantized = weight[idx], ste = (q - x) + x
// =====================================================================
__global__ __launch_bounds__(256)
void gather_kernel(const float *__restrict__ x, const float *__restrict__ w,
                   float *__restrict__ out) {
    const int b = blockIdx.y;
    const int c0 = blockIdx.x * 32;
    const int hw4 = threadIdx.x * 4;

    int4 rows = *(const int4 *)&g_idx[b * HW + hw4];
    const float *xb = x + (size_t)b * CDIM * HW + hw4;
    float *qo = out + (size_t)b * CDIM * HW + hw4;
    float *so = out + (size_t)NPIX * CDIM + (size_t)b * CDIM * HW + hw4;
    const float *w0 = w + (size_t)rows.x * CDIM;
    const float *w1 = w + (size_t)rows.y * CDIM;
    const float *w2 = w + (size_t)rows.z * CDIM;
    const float *w3 = w + (size_t)rows.w * CDIM;

#pragma unroll 4
    for (int c = c0; c < c0 + 32; c++) {
        float4 qv;
        qv.x = w0[c]; qv.y = w1[c]; qv.z = w2[c]; qv.w = w3[c];
        float4 xv = *(const float4 *)(xb + (size_t)c * HW);
        *(float4 *)(qo + (size_t)c * HW) = qv;
        float4 sv;
        sv.x = __fadd_rn(__fsub_rn(qv.x, xv.x), xv.x);
        sv.y = __fadd_rn(__fsub_rn(qv.y, xv.y), xv.y);
        sv.z = __fadd_rn(__fsub_rn(qv.z, xv.z), xv.z);
        sv.w = __fadd_rn(__fsub_rn(qv.w, xv.w), xv.w);
        *(float4 *)(so + (size_t)c * HW) = sv;
    }
}

// =====================================================================
extern "C" void kernel_launch(void *const *d_in, const int *in_sizes, int n_in,
                              void *d_out, int out_size) {
    const float *x = (const float *)d_in[0];
    const float *w = (const float *)d_in[1];
    if (n_in >= 2 && in_sizes[0] == CODES * CDIM && in_sizes[1] == NPIX * CDIM) {
        const float *tmp = x; x = w; w = tmp;
    }
    float *out = (float *)d_out;
    float *out_idxf = out + 2 * (size_t)NPIX * CDIM;

    cudaFuncSetAttribute(prep_x, cudaFuncAttributeMaxDynamicSharedMemorySize, 128 * XP * 4);
    cudaFuncSetAttribute(mma_kernel, cudaFuncAttributeMaxDynamicSharedMemorySize, SMEM_MMA);

    prep_w<<<128, 256>>>(w);
    prep_x<<<512, 256, 128 * XP * 4>>>(x);
    mma_kernel<<<512, 256, SMEM_MMA>>>(out_idxf);
    rescore2<<<512, 256>>>(w, out_idxf);
    gather_kernel<<<dim3(8, 64), 256>>>(x, w, out);
}

// round 12
// speedup vs baseline: 2.3251x; 1.0843x over previous
#include <cuda_runtime.h>
#include <cuda_fp16.h>
#include <cstdint>

#define CODES 1024
#define CDIM  256
#define HW    1024
#define NPIX  65536
#define NCHUNK 8            // 1024 codes / 128
#define NTILE  512          // 65536 px / 128

// ---------------- static scratch ----------------
__device__ __align__(1024) unsigned char g_wb[NCHUNK * 65536]; // fp16 B images (swizzled)
__device__ __align__(1024) float g_xT[(size_t)NPIX * CDIM];    // fp32 x, pixel-major (64MB)
__device__ float g_wsq[CODES];
__device__ float g_pmax[128];
__device__ float g_xx[NPIX];
__device__ float g_sx[NPIX];
__device__ int   g_cand[NPIX * 32];
__device__ float g_cs[NPIX * 32];      // approx score per candidate
__device__ int   g_cnt[NPIX];
__device__ int   g_idx[NPIX];
__device__ int   g_queue[NPIX];
__device__ int   g_qcnt;

// ---------------- helpers ----------------
__device__ __forceinline__ uint32_t smem_u32(const void *p) {
    uint32_t a;
    asm("{ .reg .u64 t; cvta.to.shared.u64 t, %1; cvt.u32.u64 %0, t; }" : "=r"(a) : "l"(p));
    return a;
}
__device__ __forceinline__ void cp16(uint32_t dst, const void *src) {
    asm volatile("cp.async.cg.shared.global [%0], [%1], 16;" :: "r"(dst), "l"(src) : "memory");
}
#define CP_COMMIT() asm volatile("cp.async.commit_group;" ::: "memory")
#define CP_WAIT1()  asm volatile("cp.async.wait_group 1;" ::: "memory")
#define CP_WAIT0()  asm volatile("cp.async.wait_group 0;" ::: "memory")

__device__ __forceinline__ uint32_t packh(float lo, float hi) {
    uint32_t r;
    asm("cvt.rn.f16x2.f32 %0, %1, %2;" : "=r"(r) : "f"(hi), "f"(lo));  // r = hi<<16 | lo
    return r;
}
// image layout: 128 rows x 256 fp16 k-major, rows of 512B = 32 16B-chunks,
// chunk swizzle: stored chunk index = chunk ^ (row & 7)  -> ldmatrix conflict-free
__device__ __forceinline__ uint32_t img_off(int row, int chunk) {
    return (uint32_t)row * 512u + (uint32_t)((chunk ^ (row & 7)) << 4);
}

__device__ __forceinline__ void ldsm_x4(uint32_t &r0, uint32_t &r1, uint32_t &r2, uint32_t &r3,
                                        uint32_t addr) {
    asm volatile("ldmatrix.sync.aligned.m8n8.x4.shared.b16 {%0,%1,%2,%3}, [%4];"
                 : "=r"(r0), "=r"(r1), "=r"(r2), "=r"(r3) : "r"(addr));
}
__device__ __forceinline__ void mma16816(float *d, uint32_t a0, uint32_t a1, uint32_t a2,
                                         uint32_t a3, uint32_t b0, uint32_t b1) {
    asm volatile("mma.sync.aligned.m16n8k16.row.col.f32.f16.f16.f32 "
                 "{%0,%1,%2,%3}, {%4,%5,%6,%7}, {%8,%9}, {%0,%1,%2,%3};"
                 : "+f"(d[0]), "+f"(d[1]), "+f"(d[2]), "+f"(d[3])
                 : "r"(a0), "r"(a1), "r"(a2), "r"(a3), "r"(b0), "r"(b1));
}

// =====================================================================
// prep_w: exact wsq, fp16 swizzled B images, per-block max|w|, zero queue
// grid 128 x 256 (8 codes/block, one warp per code)
// =====================================================================
__global__ void prep_w(const float *__restrict__ w) {
    __shared__ float wm[8];
    if (blockIdx.x == 0 && threadIdx.x == 0) g_qcnt = 0;
    int wid = threadIdx.x >> 5, lane = threadIdx.x & 31;
    int code = blockIdx.x * 8 + wid;
    const float *row = w + code * CDIM;
    float s = 0.f, pm = 0.f;
#pragma unroll
    for (int j = 0; j < 8; j++) {
        float v = row[lane + 32 * j];
        s = __fmaf_rn(v, v, s);
        pm = fmaxf(pm, fabsf(v));
    }
#pragma unroll
    for (int o = 16; o; o >>= 1) {
        s += __shfl_xor_sync(0xffffffffu, s, o);
        pm = fmaxf(pm, __shfl_xor_sync(0xffffffffu, pm, o));
    }
    if (lane == 0) { g_wsq[code] = s; wm[wid] = pm; }
    float f[8];
#pragma unroll
    for (int j = 0; j < 8; j++) f[j] = row[lane * 8 + j];
    uint4 v;
    v.x = packh(f[0], f[1]); v.y = packh(f[2], f[3]);
    v.z = packh(f[4], f[5]); v.w = packh(f[6], f[7]);
    int chunk = code >> 7, lr = code & 127;
    *(uint4 *)(g_wb + chunk * 65536 + img_off(lr, lane)) = v;
    __syncthreads();
    if (threadIdx.x == 0) {
        float m = 0.f;
        for (int i = 0; i < 8; i++) m = fmaxf(m, wm[i]);
        g_pmax[blockIdx.x] = m;
    }
}

// =====================================================================
// prep_x: per 128-pixel tile: fp32 pixel-major g_xT transpose,
//         exact sequential xx and sum|x|.  grid 512 x 256.
// =====================================================================
#define XP 131
__global__ __launch_bounds__(256) void prep_x(const float *__restrict__ x) {
    extern __shared__ float sm[];
    const int tile = blockIdx.x;
    const int b = tile >> 3, hw0 = (tile & 7) * 128;
    const int tid = threadIdx.x;
    float *xtd = g_xT + (size_t)tile * 128 * CDIM;
    float xxa = 0.f, sxa = 0.f;

    for (int h = 0; h < 2; h++) {
        const float *src = x + (size_t)b * CDIM * HW + (size_t)(h * 128) * HW + hw0;
#pragma unroll
        for (int it = 0; it < 64; it++) {
            int idx = tid + 256 * it;
            int kk = idx >> 7, p = idx & 127;
            sm[kk * XP + p] = src[(size_t)kk * HW + p];
        }
        __syncthreads();
        if (tid < 128) {
            for (int kk = 0; kk < 128; kk++) {
                float v = sm[kk * XP + tid];
                xxa = __fadd_rn(xxa, __fmul_rn(v, v));
                sxa = __fadd_rn(sxa, fabsf(v));
            }
        }
        // fp32 transpose out: g_xT[pix][h*128 + k]
        {
            int k4 = tid & 31;
            for (int pp = tid >> 5; pp < 128; pp += 8) {
                float4 v4;
                v4.x = sm[(k4 * 4 + 0) * XP + pp];
                v4.y = sm[(k4 * 4 + 1) * XP + pp];
                v4.z = sm[(k4 * 4 + 2) * XP + pp];
                v4.w = sm[(k4 * 4 + 3) * XP + pp];
                *(float4 *)(xtd + (size_t)pp * CDIM + h * 128 + k4 * 4) = v4;
            }
        }
        __syncthreads();
    }
    if (tid < 128) {
        g_xx[tile * 128 + tid] = xxa;
        g_sx[tile * 128 + tid] = sxa;
    }
}

// =====================================================================
// mma_kernel: warp tiling 4(px-groups of 32) x 2(N-halves of 64 codes).
//   A tile converted in-kernel from g_xT (no g_xb round-trip).
//   Per ks: 2 A-LDSM + 4 B-LDSM + 16 MMA. Double-buffered B.
//   ONE syncthreads per chunk: push vs min(stale-global, warp-min)+TH
//   (looser -> still superset); tail refilters vs FINAL global min.
// grid 512 x 256
// =====================================================================
#define SM_WSQ 0
#define SM_CNT 4096
#define SM_RUN 5120
#define SM_A   8192
#define SM_B0  73728
#define SM_B1  139264
#define SMEM_MMA 204800

__device__ __forceinline__ void copy_img(uint32_t dst, const unsigned char *src, int tid) {
#pragma unroll
    for (int i = 0; i < 16; i++) {
        int c = tid + 256 * i;        // 4096 chunks of 16B
        cp16(dst + (uint32_t)c * 16u, src + (size_t)c * 16u);
    }
}

__global__ __launch_bounds__(256, 1) void mma_kernel(float *__restrict__ out_idxf) {
    extern __shared__ char smc[];
    uint32_t sb = smem_u32(smc);
    float *wsq_s = (float *)(smc + SM_WSQ);
    int *cnt_s = (int *)(smc + SM_CNT);
    int *run_s = (int *)(smc + SM_RUN);
    const int tid = threadIdx.x, warp = tid >> 5, lane = tid & 31;
    const int tile = blockIdx.x;
    const int wM = warp & 3;        // pixel group: 32 px
    const int wN = warp >> 2;       // code half: 64 codes
    const int m0 = wM * 32;

    copy_img(sb + SM_B0, g_wb, tid);
    CP_COMMIT();

    // A tile: convert g_xT fp32 -> fp16 swizzled smem (overlaps B prefetch)
    {
        const float *xt = g_xT + (size_t)tile * 128 * CDIM;
#pragma unroll
        for (int i = 0; i < 16; i++) {
            int cch = tid + 256 * i;          // 4096 chunks
            int row = cch >> 5, ch = cch & 31;
            const float4 *src4 = (const float4 *)(xt + row * CDIM + ch * 8);
            float4 f0 = src4[0], f1 = src4[1];
            uint4 v;
            v.x = packh(f0.x, f0.y); v.y = packh(f0.z, f0.w);
            v.z = packh(f1.x, f1.y); v.w = packh(f1.z, f1.w);
            *(uint4 *)(smc + SM_A + img_off(row, ch)) = v;
        }
    }

    for (int i = tid; i < CODES; i += 256) wsq_s[i] = g_wsq[i];
    if (tid < 128) {
        cnt_s[tid] = 0;
        run_s[tid] = 0x7f800000;           // +inf
    }
    if (tid == 0) {
        float m = 0.f;
        for (int i = 0; i < 128; i++) m = fmaxf(m, g_pmax[i]);
        ((float *)(smc + SM_CNT))[130] = m;
    }
    __syncthreads();
    const float wmax = ((float *)(smc + SM_CNT))[130];

    // 4 pixel rows per thread: [f][r] = m0 + f*16 + r*8 + (lane>>2)
    const int pr = lane >> 2;
    float xxv[2][2], THv[2][2];
#pragma unroll
    for (int f = 0; f < 2; f++)
#pragma unroll
        for (int r = 0; r < 2; r++) {
            int pix = tile * 128 + m0 + f * 16 + r * 8 + pr;
            xxv[f][r] = g_xx[pix];
            THv[f][r] = __fmaf_rn(g_sx[pix] * wmax, 0.006f, 4e-4f);   // fp16 bound, 1.5x safety
        }

    // ldmatrix addressing
    const int mat = lane >> 3, r7 = lane & 7;
    const int a_row0 = m0 + r7 + ((mat & 1) << 3);
    const int a_cadd = mat >> 1;
    const uint32_t a_base0 = sb + SM_A + (uint32_t)a_row0 * 512u;       // f=0
    const uint32_t a_base1 = a_base0 + 16u * 512u;                      // f=1
    const int b_rowoff = r7 + ((mat >> 1) << 3);
    const int b_cadd = mat & 1;
    const uint32_t b_roff = (uint32_t)(wN * 64) * 512u + (uint32_t)b_rowoff * 512u;

    for (int c = 0; c < NCHUNK; c++) {
        if (c < 7) {
            copy_img(sb + (((c + 1) & 1) ? SM_B1 : SM_B0), g_wb + (size_t)(c + 1) * 65536, tid);
            CP_COMMIT();
            CP_WAIT1();
        } else {
            CP_WAIT0();
        }
        __syncthreads();   // buffer guard + makes prev-chunk atomicMins visible

        const uint32_t b_base = sb + ((c & 1) ? SM_B1 : SM_B0) + b_roff;

        float acc[2][8][4];
#pragma unroll
        for (int f = 0; f < 2; f++)
#pragma unroll
            for (int nb = 0; nb < 8; nb++)
#pragma unroll
                for (int j = 0; j < 4; j++) acc[f][nb][j] = 0.f;

#pragma unroll
        for (int ks = 0; ks < 16; ks++) {
            const uint32_t koff = (uint32_t)(((2 * ks + a_cadd) ^ r7) << 4);
            const uint32_t koffb = (uint32_t)(((2 * ks + b_cadd) ^ r7) << 4);
            uint32_t a00, a01, a02, a03, a10, a11, a12, a13;
            ldsm_x4(a00, a01, a02, a03, a_base0 + koff);
            ldsm_x4(a10, a11, a12, a13, a_base1 + koff);
#pragma unroll
            for (int g = 0; g < 4; g++) {
                uint32_t b0, b1, b2, b3;
                ldsm_x4(b0, b1, b2, b3, b_base + (uint32_t)(g * 8192) + koffb);
                mma16816(acc[0][2 * g],     a00, a01, a02, a03, b0, b1);
                mma16816(acc[0][2 * g + 1], a00, a01, a02, a03, b2, b3);
                mma16816(acc[1][2 * g],     a10, a11, a12, a13, b0, b1);
                mma16816(acc[1][2 * g + 1], a10, a11, a12, a13, b2, b3);
            }
        }

        // ---- epilogue: scores, quad-min, push vs min(stale-global, warpmin) ----
        const int ncol = 2 * (lane & 3);
        const int code0 = c * 128 + wN * 64 + ncol;
        float lm[2][2];
        lm[0][0] = lm[0][1] = lm[1][0] = lm[1][1] = __int_as_float(0x7f800000);
#pragma unroll
        for (int f = 0; f < 2; f++)
#pragma unroll
            for (int nb = 0; nb < 8; nb++) {
                const float *wq = wsq_s + c * 128 + wN * 64 + nb * 8 + ncol;
                float s;
                s = __fadd_rn(__fmaf_rn(-2.f, acc[f][nb][0], xxv[f][0]), wq[0]); acc[f][nb][0] = s; lm[f][0] = fminf(lm[f][0], s);
                s = __fadd_rn(__fmaf_rn(-2.f, acc[f][nb][1], xxv[f][0]), wq[1]); acc[f][nb][1] = s; lm[f][0] = fminf(lm[f][0], s);
                s = __fadd_rn(__fmaf_rn(-2.f, acc[f][nb][2], xxv[f][1]), wq[0]); acc[f][nb][2] = s; lm[f][1] = fminf(lm[f][1], s);
                s = __fadd_rn(__fmaf_rn(-2.f, acc[f][nb][3], xxv[f][1]), wq[1]); acc[f][nb][3] = s; lm[f][1] = fminf(lm[f][1], s);
            }
#pragma unroll
        for (int o = 1; o <= 2; o <<= 1)
#pragma unroll
            for (int f = 0; f < 2; f++)
#pragma unroll
                for (int r = 0; r < 2; r++)
                    lm[f][r] = fminf(lm[f][r], __shfl_xor_sync(0xffffffffu, lm[f][r], o));

#pragma unroll
        for (int f = 0; f < 2; f++)
#pragma unroll
            for (int r = 0; r < 2; r++) {
                const int pxl = m0 + f * 16 + r * 8 + pr;
                const int pix = tile * 128 + pxl;
                const float th = fminf(__int_as_float(run_s[pxl]), lm[f][r]) + THv[f][r];
#pragma unroll
                for (int nb = 0; nb < 8; nb++) {
                    int cb = code0 + nb * 8;
                    float s0 = acc[f][nb][2 * r], s1 = acc[f][nb][2 * r + 1];
                    if (s0 <= th) {
                        int sl = atomicAdd(&cnt_s[pxl], 1);
                        if (sl < 32) {
                            g_cand[(size_t)pix * 32 + sl] = cb;
                            g_cs[(size_t)pix * 32 + sl] = s0;
                        }
                    }
                    if (s1 <= th) {
                        int sl = atomicAdd(&cnt_s[pxl], 1);
                        if (sl < 32) {
                            g_cand[(size_t)pix * 32 + sl] = cb + 1;
                            g_cs[(size_t)pix * 32 + sl] = s1;
                        }
                    }
                }
            }
        if ((lane & 3) == 0) {
#pragma unroll
            for (int f = 0; f < 2; f++)
#pragma unroll
                for (int r = 0; r < 2; r++)
                    atomicMin(&run_s[m0 + f * 16 + r * 8 + pr], __float_as_int(lm[f][r]));
        }
    }
    __syncthreads();   // final runmin + counters visible

    // ---- tail: refilter candidates against FINAL runmin, finalize or queue ----
    if (tid < 128) {
        int pix = tile * 128 + tid;
        int cnt = cnt_s[tid];
        if (cnt > 32) {
            g_cnt[pix] = cnt;                       // overflow -> full-scan path
            int q = atomicAdd(&g_qcnt, 1);
            g_queue[q] = pix;
        } else {
            const float th = __int_as_float(run_s[tid]) +
                             __fmaf_rn(g_sx[pix] * wmax, 0.006f, 4e-4f);
            int nk = 0, first = 0;
            for (int j = 0; j < cnt; j++) {
                int code = g_cand[(size_t)pix * 32 + j];
                float s = g_cs[(size_t)pix * 32 + j];
                if (s <= th) {
                    g_cand[(size_t)pix * 32 + nk] = code;   // in-place compact (nk<=j)
                    if (nk == 0) first = code;
                    nk++;
                }
            }
            g_cnt[pix] = nk;
            if (nk == 1) {
                g_idx[pix] = first;
                out_idxf[pix] = (float)first;
            } else {
                int q = atomicAdd(&g_qcnt, 1);
                g_queue[q] = pix;
            }
        }
    }
}

// =====================================================================
// rescore2: warp per queued pixel, one candidate per lane, exact fp32
//   chain (sequential ascending k). x from pixel-major g_xT.
// grid 512 x 256
// =====================================================================
__global__ __launch_bounds__(256) void rescore2(const float *__restrict__ w,
                                                float *__restrict__ out_idxf) {
    const int lane = threadIdx.x & 31;
    const int gwarp = (blockIdx.x * blockDim.x + threadIdx.x) >> 5;
    const int nwarp = (gridDim.x * blockDim.x) >> 5;
    const int total = g_qcnt;
    const float INF = __int_as_float(0x7f800000);

    for (int q = gwarp; q < total; q += nwarp) {
        int pix = g_queue[q];
        int cnt = g_cnt[pix];
        float xxp = g_xx[pix];
        const float4 *xb4 = (const float4 *)(g_xT + (size_t)pix * CDIM);

        float bestd = INF;
        int besti = CODES;
        int nloop = (cnt > 32) ? 32 : 1;   // overflow -> stripe all 1024 codes

        for (int t = 0; t < nloop; t++) {
            int cidx;
            bool active;
            if (cnt > 32) { cidx = t * 32 + lane; active = true; }
            else          { cidx = (lane < cnt) ? g_cand[(size_t)pix * 32 + lane] : 0; active = (lane < cnt); }

            if (active) {
                const float4 *wr = (const float4 *)(w + (size_t)cidx * CDIM);
                float dot = 0.f;
#pragma unroll 8
                for (int qq = 0; qq < 64; qq++) {
                    float4 wv = wr[qq];
                    float4 xv = xb4[qq];
                    dot = __fmaf_rn(xv.x, wv.x, dot);
                    dot = __fmaf_rn(xv.y, wv.y, dot);
                    dot = __fmaf_rn(xv.z, wv.z, dot);
                    dot = __fmaf_rn(xv.w, wv.w, dot);
                }
                float d = __fadd_rn(__fmaf_rn(-2.f, dot, xxp), g_wsq[cidx]);
                if (d < bestd || (d == bestd && cidx < besti)) { bestd = d; besti = cidx; }
            }
        }
#pragma unroll
        for (int o = 16; o; o >>= 1) {
            float od = __shfl_xor_sync(0xffffffffu, bestd, o);
            int   oi = __shfl_xor_sync(0xffffffffu, besti, o);
            if (od < bestd || (od == bestd && oi < besti)) { bestd = od; besti = oi; }
        }
        if (lane == 0) {
            g_idx[pix] = besti;
            out_idxf[pix] = (float)besti;
        }
    }
}

// =====================================================================
// gather: quantized = weight[idx], ste = (q - x) + x
//   Thread-per-pixel contiguous w-row reads -> smem transpose -> coalesced
//   stores.  grid (8, 64) x 256, 4 sub-iterations of 256 pixels.
// =====================================================================
#define QS 257
__global__ __launch_bounds__(256)
void gather_kernel(const float *__restrict__ x, const float *__restrict__ w,
                   float *__restrict__ out) {
    __shared__ float qsm[32 * QS];
    const int b = blockIdx.y;
    const int c0 = blockIdx.x * 32;
    const int tid = threadIdx.x;

    const float *xb = x + (size_t)b * CDIM * HW;
    float *qo = out + (size_t)b * CDIM * HW;
    float *so = out + (size_t)NPIX * CDIM + (size_t)b * CDIM * HW;

    for (int sub = 0; sub < 4; sub++) {
        const int px = sub * 256 + tid;
        int row = g_idx[b * HW + px];
        const float4 *wr = (const float4 *)(w + (size_t)row * CDIM + c0);
#pragma unroll
        for (int j = 0; j < 8; j++) {
            float4 v = wr[j];
            qsm[(4 * j + 0) * QS + tid] = v.x;
            qsm[(4 * j + 1) * QS + tid] = v.y;
            qsm[(4 * j + 2) * QS + tid] = v.z;
            qsm[(4 * j + 3) * QS + tid] = v.w;
        }
        __syncthreads();
#pragma unroll 4
        for (int c = 0; c < 32; c++) {
            size_t off = (size_t)(c0 + c) * HW + sub * 256 + tid;
            float qv = qsm[c * QS + tid];
            float xv = xb[off];
            qo[off] = qv;
            so[off] = __fadd_rn(__fsub_rn(qv, xv), xv);
        }
        __syncthreads();
    }
}

// =====================================================================
extern "C" void kernel_launch(void *const *d_in, const int *in_sizes, int n_in,
                              void *d_out, int out_size) {
    const float *x = (const float *)d_in[0];
    const float *w = (const float *)d_in[1];
    if (n_in >= 2 && in_sizes[0] == CODES * CDIM && in_sizes[1] == NPIX * CDIM) {
        const float *tmp = x; x = w; w = tmp;
    }
    float *out = (float *)d_out;
    float *out_idxf = out + 2 * (size_t)NPIX * CDIM;

    cudaFuncSetAttribute(prep_x, cudaFuncAttributeMaxDynamicSharedMemorySize, 128 * XP * 4);
    cudaFuncSetAttribute(mma_kernel, cudaFuncAttributeMaxDynamicSharedMemorySize, SMEM_MMA);

    prep_w<<<128, 256>>>(w);
    prep_x<<<512, 256, 128 * XP * 4>>>(x);
    mma_kernel<<<512, 256, SMEM_MMA>>>(out_idxf);
    rescore2<<<512, 256>>>(w, out_idxf);
    gather_kernel<<<dim3(8, 64), 256>>>(x, w, out);
}

// round 13
// speedup vs baseline: 2.5624x; 1.1021x over previous
#include <cuda_runtime.h>
#include <cuda_fp16.h>
#include <cstdint>

#define CODES 1024
#define CDIM  256
#define HW    1024
#define NPIX  65536
#define NCHUNK 8            // 1024 codes / 128
#define NTILE  512          // 65536 px / 128

// ---------------- static scratch ----------------
__device__ __align__(1024) unsigned char g_wb[NCHUNK * 65536]; // fp16 B images (swizzled)
__device__ __align__(1024) float g_xT[(size_t)NPIX * CDIM];    // fp32 x, pixel-major (64MB)
__device__ float g_wsq[CODES];
__device__ float g_pmax[128];
__device__ float g_xx[NPIX];
__device__ int   g_cand[NPIX * 32];
__device__ float g_cs[NPIX * 32];      // approx score per candidate
__device__ int   g_cnt[NPIX];
__device__ int   g_idx[NPIX];
__device__ int   g_queue[NPIX];
__device__ int   g_qcnt;

// ---------------- helpers ----------------
__device__ __forceinline__ uint32_t smem_u32(const void *p) {
    uint32_t a;
    asm("{ .reg .u64 t; cvta.to.shared.u64 t, %1; cvt.u32.u64 %0, t; }" : "=r"(a) : "l"(p));
    return a;
}
__device__ __forceinline__ void cp16(uint32_t dst, const void *src) {
    asm volatile("cp.async.cg.shared.global [%0], [%1], 16;" :: "r"(dst), "l"(src) : "memory");
}
#define CP_COMMIT() asm volatile("cp.async.commit_group;" ::: "memory")
#define CP_WAIT1()  asm volatile("cp.async.wait_group 1;" ::: "memory")
#define CP_WAIT0()  asm volatile("cp.async.wait_group 0;" ::: "memory")

__device__ __forceinline__ uint32_t packh(float lo, float hi) {
    uint32_t r;
    asm("cvt.rn.f16x2.f32 %0, %1, %2;" : "=r"(r) : "f"(hi), "f"(lo));  // r = hi<<16 | lo
    return r;
}
// image layout: 128 rows x 256 fp16 k-major, rows of 512B = 32 16B-chunks,
// chunk swizzle: stored chunk index = chunk ^ (row & 7)  -> ldmatrix conflict-free
__device__ __forceinline__ uint32_t img_off(int row, int chunk) {
    return (uint32_t)row * 512u + (uint32_t)((chunk ^ (row & 7)) << 4);
}

__device__ __forceinline__ void ldsm_x4(uint32_t &r0, uint32_t &r1, uint32_t &r2, uint32_t &r3,
                                        uint32_t addr) {
    asm volatile("ldmatrix.sync.aligned.m8n8.x4.shared.b16 {%0,%1,%2,%3}, [%4];"
                 : "=r"(r0), "=r"(r1), "=r"(r2), "=r"(r3) : "r"(addr));
}
__device__ __forceinline__ void mma16816(float *d, uint32_t a0, uint32_t a1, uint32_t a2,
                                         uint32_t a3, uint32_t b0, uint32_t b1) {
    asm volatile("mma.sync.aligned.m16n8k16.row.col.f32.f16.f16.f32 "
                 "{%0,%1,%2,%3}, {%4,%5,%6,%7}, {%8,%9}, {%0,%1,%2,%3};"
                 : "+f"(d[0]), "+f"(d[1]), "+f"(d[2]), "+f"(d[3])
                 : "r"(a0), "r"(a1), "r"(a2), "r"(a3), "r"(b0), "r"(b1));
}

// =====================================================================
// prep_w: exact wsq, fp16 swizzled B images, per-block max|w|, zero queue
// grid 128 x 256 (8 codes/block, one warp per code)
// =====================================================================
__global__ void prep_w(const float *__restrict__ w) {
    __shared__ float wm[8];
    if (blockIdx.x == 0 && threadIdx.x == 0) g_qcnt = 0;
    int wid = threadIdx.x >> 5, lane = threadIdx.x & 31;
    int code = blockIdx.x * 8 + wid;
    const float *row = w + code * CDIM;
    float s = 0.f, pm = 0.f;
#pragma unroll
    for (int j = 0; j < 8; j++) {
        float v = row[lane + 32 * j];
        s = __fmaf_rn(v, v, s);
        pm = fmaxf(pm, fabsf(v));
    }
#pragma unroll
    for (int o = 16; o; o >>= 1) {
        s += __shfl_xor_sync(0xffffffffu, s, o);
        pm = fmaxf(pm, __shfl_xor_sync(0xffffffffu, pm, o));
    }
    if (lane == 0) { g_wsq[code] = s; wm[wid] = pm; }
    float f[8];
#pragma unroll
    for (int j = 0; j < 8; j++) f[j] = row[lane * 8 + j];
    uint4 v;
    v.x = packh(f[0], f[1]); v.y = packh(f[2], f[3]);
    v.z = packh(f[4], f[5]); v.w = packh(f[6], f[7]);
    int chunk = code >> 7, lr = code & 127;
    *(uint4 *)(g_wb + chunk * 65536 + img_off(lr, lane)) = v;
    __syncthreads();
    if (threadIdx.x == 0) {
        float m = 0.f;
        for (int i = 0; i < 8; i++) m = fmaxf(m, wm[i]);
        g_pmax[blockIdx.x] = m;
    }
}

// =====================================================================
// mma_kernel (fused prep_x): stages x fp32 in smem, computes exact stats,
//   converts fp16 A tile in-place, writes pixel-major g_xT (for rescore).
//   Warp tiling 4(px-groups of 32) x 2(N-halves of 64 codes).
//   Per ks: 2 A-LDSM + 4 B-LDSM + 16 MMA. Double-buffered B.
//   ONE syncthreads per chunk; tail refilters vs FINAL global min.
// grid 512 x 256
// =====================================================================
#define SM_WSQ 0
#define SM_CNT 4096
#define SM_RUN 5120
#define SM_XX  5632
#define SM_SX  6144
#define SM_A   8192
#define SM_B0  73728
#define SM_B1  139264
#define SM_STG 73728                       // fp32 staging overlays B0/B1
#define XSP    131
#define SMEM_MMA (SM_STG + 256 * XSP * 4)  // 207872

__device__ __forceinline__ void copy_img(uint32_t dst, const unsigned char *src, int tid) {
#pragma unroll
    for (int i = 0; i < 16; i++) {
        int c = tid + 256 * i;        // 4096 chunks of 16B
        cp16(dst + (uint32_t)c * 16u, src + (size_t)c * 16u);
    }
}

__global__ __launch_bounds__(256, 1) void mma_kernel(const float *__restrict__ x,
                                                     float *__restrict__ out_idxf) {
    extern __shared__ char smc[];
    uint32_t sb = smem_u32(smc);
    float *wsq_s = (float *)(smc + SM_WSQ);
    int *cnt_s = (int *)(smc + SM_CNT);
    int *run_s = (int *)(smc + SM_RUN);
    float *xx_s = (float *)(smc + SM_XX);
    float *sx_s = (float *)(smc + SM_SX);
    float *stg = (float *)(smc + SM_STG);
    const int tid = threadIdx.x, warp = tid >> 5, lane = tid & 31;
    const int tile = blockIdx.x;
    const int b = tile >> 3, hw0 = (tile & 7) * 128;
    const int wM = warp & 3;        // pixel group: 32 px
    const int wN = warp >> 2;       // code half: 64 codes
    const int m0 = wM * 32;

    // ---- stage x tile fp32 (coalesced k-major loads) ----
    {
        const float *src = x + (size_t)b * CDIM * HW + hw0;
#pragma unroll
        for (int it = 0; it < 128; it++) {
            int idx = tid + 256 * it;
            int kk = idx >> 7, p = idx & 127;
            stg[kk * XSP + p] = src[(size_t)kk * HW + p];
        }
    }
    for (int i = tid; i < CODES; i += 256) wsq_s[i] = g_wsq[i];
    if (tid < 128) {
        cnt_s[tid] = 0;
        run_s[tid] = 0x7f800000;           // +inf
    }
    if (tid == 0) {
        float m = 0.f;
        for (int i = 0; i < 128; i++) m = fmaxf(m, g_pmax[i]);
        ((float *)(smc + SM_CNT))[130] = m;
    }
    __syncthreads();

    // ---- exact sequential stats (identical op order to old prep_x) ----
    if (tid < 128) {
        float xxa = 0.f, sxa = 0.f;
        for (int kk = 0; kk < 256; kk++) {
            float v = stg[kk * XSP + tid];
            xxa = __fadd_rn(xxa, __fmul_rn(v, v));
            sxa = __fadd_rn(sxa, fabsf(v));
        }
        xx_s[tid] = xxa;
        sx_s[tid] = sxa;
        g_xx[tile * 128 + tid] = xxa;
    }
    // ---- convert to fp16 swizzled A tile ----
    {
        int p = tid & 127;
#pragma unroll
        for (int it = 0; it < 16; it++) {
            int oct = (tid >> 7) * 16 + it;          // 0..31
            float f[8];
#pragma unroll
            for (int j = 0; j < 8; j++) f[j] = stg[(oct * 8 + j) * XSP + p];
            uint4 v;
            v.x = packh(f[0], f[1]); v.y = packh(f[2], f[3]);
            v.z = packh(f[4], f[5]); v.w = packh(f[6], f[7]);
            *(uint4 *)(smc + SM_A + img_off(p, oct));
            *(uint4 *)(smc + SM_A + img_off(p, oct)) = v;
        }
    }
    // ---- write pixel-major fp32 g_xT (coalesced float4) ----
    {
        float *xtd = g_xT + (size_t)tile * 128 * CDIM;
        int k4 = tid & 63;                  // 64 float4 per pixel
        for (int pp = tid >> 6; pp < 128; pp += 4) {
            float4 v4;
            v4.x = stg[(k4 * 4 + 0) * XSP + pp];
            v4.y = stg[(k4 * 4 + 1) * XSP + pp];
            v4.z = stg[(k4 * 4 + 2) * XSP + pp];
            v4.w = stg[(k4 * 4 + 3) * XSP + pp];
            *(float4 *)(xtd + (size_t)pp * CDIM + k4 * 4) = v4;
        }
    }
    __syncthreads();   // staging reads done -> B prefetch may overwrite

    const float wmax = ((float *)(smc + SM_CNT))[130];

    // first B chunk prefetch
    copy_img(sb + SM_B0, g_wb, tid);
    CP_COMMIT();

    // 4 pixel rows per thread: [f][r] = m0 + f*16 + r*8 + (lane>>2)
    const int pr = lane >> 2;
    float xxv[2][2], THv[2][2];
#pragma unroll
    for (int f = 0; f < 2; f++)
#pragma unroll
        for (int r = 0; r < 2; r++) {
            int pxl = m0 + f * 16 + r * 8 + pr;
            xxv[f][r] = xx_s[pxl];
            THv[f][r] = __fmaf_rn(sx_s[pxl] * wmax, 0.006f, 4e-4f);   // fp16 bound, 1.5x safety
        }

    // ldmatrix addressing
    const int mat = lane >> 3, r7 = lane & 7;
    const int a_row0 = m0 + r7 + ((mat & 1) << 3);
    const int a_cadd = mat >> 1;
    const uint32_t a_base0 = sb + SM_A + (uint32_t)a_row0 * 512u;       // f=0
    const uint32_t a_base1 = a_base0 + 16u * 512u;                      // f=1
    const int b_rowoff = r7 + ((mat >> 1) << 3);
    const int b_cadd = mat & 1;
    const uint32_t b_roff = (uint32_t)(wN * 64) * 512u + (uint32_t)b_rowoff * 512u;

    for (int c = 0; c < NCHUNK; c++) {
        if (c < 7) {
            copy_img(sb + (((c + 1) & 1) ? SM_B1 : SM_B0), g_wb + (size_t)(c + 1) * 65536, tid);
            CP_COMMIT();
            CP_WAIT1();
        } else {
            CP_WAIT0();
        }
        __syncthreads();   // buffer guard + makes prev-chunk atomicMins visible

        const uint32_t b_base = sb + ((c & 1) ? SM_B1 : SM_B0) + b_roff;

        float acc[2][8][4];
#pragma unroll
        for (int f = 0; f < 2; f++)
#pragma unroll
            for (int nb = 0; nb < 8; nb++)
#pragma unroll
                for (int j = 0; j < 4; j++) acc[f][nb][j] = 0.f;

#pragma unroll
        for (int ks = 0; ks < 16; ks++) {
            const uint32_t koff = (uint32_t)(((2 * ks + a_cadd) ^ r7) << 4);
            const uint32_t koffb = (uint32_t)(((2 * ks + b_cadd) ^ r7) << 4);
            uint32_t a00, a01, a02, a03, a10, a11, a12, a13;
            ldsm_x4(a00, a01, a02, a03, a_base0 + koff);
            ldsm_x4(a10, a11, a12, a13, a_base1 + koff);
#pragma unroll
            for (int g = 0; g < 4; g++) {
                uint32_t b0, b1, b2, b3;
                ldsm_x4(b0, b1, b2, b3, b_base + (uint32_t)(g * 8192) + koffb);
                mma16816(acc[0][2 * g],     a00, a01, a02, a03, b0, b1);
                mma16816(acc[0][2 * g + 1], a00, a01, a02, a03, b2, b3);
                mma16816(acc[1][2 * g],     a10, a11, a12, a13, b0, b1);
                mma16816(acc[1][2 * g + 1], a10, a11, a12, a13, b2, b3);
            }
        }

        // ---- epilogue: scores, quad-min, push vs min(stale-global, warpmin) ----
        const int ncol = 2 * (lane & 3);
        const int code0 = c * 128 + wN * 64 + ncol;
        float lm[2][2];
        lm[0][0] = lm[0][1] = lm[1][0] = lm[1][1] = __int_as_float(0x7f800000);
#pragma unroll
        for (int f = 0; f < 2; f++)
#pragma unroll
            for (int nb = 0; nb < 8; nb++) {
                const float *wq = wsq_s + c * 128 + wN * 64 + nb * 8 + ncol;
                float s;
                s = __fadd_rn(__fmaf_rn(-2.f, acc[f][nb][0], xxv[f][0]), wq[0]); acc[f][nb][0] = s; lm[f][0] = fminf(lm[f][0], s);
                s = __fadd_rn(__fmaf_rn(-2.f, acc[f][nb][1], xxv[f][0]), wq[1]); acc[f][nb][1] = s; lm[f][0] = fminf(lm[f][0], s);
                s = __fadd_rn(__fmaf_rn(-2.f, acc[f][nb][2], xxv[f][1]), wq[0]); acc[f][nb][2] = s; lm[f][1] = fminf(lm[f][1], s);
                s = __fadd_rn(__fmaf_rn(-2.f, acc[f][nb][3], xxv[f][1]), wq[1]); acc[f][nb][3] = s; lm[f][1] = fminf(lm[f][1], s);
            }
#pragma unroll
        for (int o = 1; o <= 2; o <<= 1)
#pragma unroll
            for (int f = 0; f < 2; f++)
#pragma unroll
                for (int r = 0; r < 2; r++)
                    lm[f][r] = fminf(lm[f][r], __shfl_xor_sync(0xffffffffu, lm[f][r], o));

#pragma unroll
        for (int f = 0; f < 2; f++)
#pragma unroll
            for (int r = 0; r < 2; r++) {
                const int pxl = m0 + f * 16 + r * 8 + pr;
                const int pix = tile * 128 + pxl;
                const float th = fminf(__int_as_float(run_s[pxl]), lm[f][r]) + THv[f][r];
#pragma unroll
                for (int nb = 0; nb < 8; nb++) {
                    int cb = code0 + nb * 8;
                    float s0 = acc[f][nb][2 * r], s1 = acc[f][nb][2 * r + 1];
                    if (s0 <= th) {
                        int sl = atomicAdd(&cnt_s[pxl], 1);
                        if (sl < 32) {
                            g_cand[(size_t)pix * 32 + sl] = cb;
                            g_cs[(size_t)pix * 32 + sl] = s0;
                        }
                    }
                    if (s1 <= th) {
                        int sl = atomicAdd(&cnt_s[pxl], 1);
                        if (sl < 32) {
                            g_cand[(size_t)pix * 32 + sl] = cb + 1;
                            g_cs[(size_t)pix * 32 + sl] = s1;
                        }
                    }
                }
            }
        if ((lane & 3) == 0) {
#pragma unroll
            for (int f = 0; f < 2; f++)
#pragma unroll
                for (int r = 0; r < 2; r++)
                    atomicMin(&run_s[m0 + f * 16 + r * 8 + pr], __float_as_int(lm[f][r]));
        }
    }
    __syncthreads();   // final runmin + counters visible

    // ---- tail: refilter candidates against FINAL runmin, finalize or queue ----
    if (tid < 128) {
        int pix = tile * 128 + tid;
        int cnt = cnt_s[tid];
        if (cnt > 32) {
            g_cnt[pix] = cnt;                       // overflow -> full-scan path
            int q = atomicAdd(&g_qcnt, 1);
            g_queue[q] = pix;
        } else {
            const float th = __int_as_float(run_s[tid]) +
                             __fmaf_rn(sx_s[tid] * wmax, 0.006f, 4e-4f);
            int nk = 0, first = 0;
            for (int j = 0; j < cnt; j++) {
                int code = g_cand[(size_t)pix * 32 + j];
                float s = g_cs[(size_t)pix * 32 + j];
                if (s <= th) {
                    g_cand[(size_t)pix * 32 + nk] = code;   // in-place compact (nk<=j)
                    if (nk == 0) first = code;
                    nk++;
                }
            }
            g_cnt[pix] = nk;
            if (nk == 1) {
                g_idx[pix] = first;
                out_idxf[pix] = (float)first;
            } else {
                int q = atomicAdd(&g_qcnt, 1);
                g_queue[q] = pix;
            }
        }
    }
}

// =====================================================================
// rescore2: 4 pixels per warp, 8 lanes per pixel; one candidate per lane
//   stride 8. Exact fp32 chain (sequential ascending k). x from g_xT.
// grid 512 x 256
// =====================================================================
__global__ __launch_bounds__(256) void rescore2(const float *__restrict__ w,
                                                float *__restrict__ out_idxf) {
    const int lane = threadIdx.x & 31;
    const int sg = lane >> 3;            // subgroup 0..3 (pixel slot)
    const int lid8 = lane & 7;
    const int gwarp = (blockIdx.x * blockDim.x + threadIdx.x) >> 5;
    const int nwarp = (gridDim.x * blockDim.x) >> 5;
    const int total = g_qcnt;
    const float INF = __int_as_float(0x7f800000);

    for (int qb = gwarp * 4; qb < total; qb += nwarp * 4) {
        int q = qb + sg;
        bool valid = (q < total);
        int pix = 0, cnt = 0;
        float xxp = 0.f;
        if (valid) {
            pix = g_queue[q];
            cnt = g_cnt[pix];
            xxp = g_xx[pix];
        }
        const float4 *xb4 = (const float4 *)(g_xT + (size_t)pix * CDIM);

        float bestd = INF;
        int besti = CODES;
        int scanN = (cnt > 32) ? CODES : cnt;   // overflow -> full scan

        for (int t = lid8; t < scanN; t += 8) {
            int cidx = (cnt > 32) ? t : g_cand[(size_t)pix * 32 + t];
            const float4 *wr = (const float4 *)(w + (size_t)cidx * CDIM);
            float dot = 0.f;
#pragma unroll 8
            for (int qq = 0; qq < 64; qq++) {
                float4 wv = wr[qq];
                float4 xv = xb4[qq];
                dot = __fmaf_rn(xv.x, wv.x, dot);
                dot = __fmaf_rn(xv.y, wv.y, dot);
                dot = __fmaf_rn(xv.z, wv.z, dot);
                dot = __fmaf_rn(xv.w, wv.w, dot);
            }
            float d = __fadd_rn(__fmaf_rn(-2.f, dot, xxp), g_wsq[cidx]);
            if (d < bestd || (d == bestd && cidx < besti)) { bestd = d; besti = cidx; }
        }
        // reduce across the 8 lanes of this subgroup (xor offsets stay in-group)
#pragma unroll
        for (int o = 1; o <= 4; o <<= 1) {
            float od = __shfl_xor_sync(0xffffffffu, bestd, o);
            int   oi = __shfl_xor_sync(0xffffffffu, besti, o);
            if (od < bestd || (od == bestd && oi < besti)) { bestd = od; besti = oi; }
        }
        if (valid && lid8 == 0) {
            g_idx[pix] = besti;
            out_idxf[pix] = (float)besti;
        }
    }
}

// =====================================================================
// gather: quantized = weight[idx], ste = (q - x) + x
//   Thread-per-pixel contiguous w-row reads -> smem transpose -> coalesced
//   stores.  grid (8, 64) x 256, 4 sub-iterations of 256 pixels.
// =====================================================================
#define QS 257
__global__ __launch_bounds__(256)
void gather_kernel(const float *__restrict__ x, const float *__restrict__ w,
                   float *__restrict__ out) {
    __shared__ float qsm[32 * QS];
    const int b = blockIdx.y;
    const int c0 = blockIdx.x * 32;
    const int tid = threadIdx.x;

    const float *xb = x + (size_t)b * CDIM * HW;
    float *qo = out + (size_t)b * CDIM * HW;
    float *so = out + (size_t)NPIX * CDIM + (size_t)b * CDIM * HW;

    for (int sub = 0; sub < 4; sub++) {
        const int px = sub * 256 + tid;
        int row = g_idx[b * HW + px];
        const float4 *wr = (const float4 *)(w + (size_t)row * CDIM + c0);
#pragma unroll
        for (int j = 0; j < 8; j++) {
            float4 v = wr[j];
            qsm[(4 * j + 0) * QS + tid] = v.x;
            qsm[(4 * j + 1) * QS + tid] = v.y;
            qsm[(4 * j + 2) * QS + tid] = v.z;
            qsm[(4 * j + 3) * QS + tid] = v.w;
        }
        __syncthreads();
#pragma unroll 4
        for (int c = 0; c < 32; c++) {
            size_t off = (size_t)(c0 + c) * HW + sub * 256 + tid;
            float qv = qsm[c * QS + tid];
            float xv = xb[off];
            qo[off] = qv;
            so[off] = __fadd_rn(__fsub_rn(qv, xv), xv);
        }
        __syncthreads();
    }
}

// =====================================================================
extern "C" void kernel_launch(void *const *d_in, const int *in_sizes, int n_in,
                              void *d_out, int out_size) {
    const float *x = (const float *)d_in[0];
    const float *w = (const float *)d_in[1];
    if (n_in >= 2 && in_sizes[0] == CODES * CDIM && in_sizes[1] == NPIX * CDIM) {
        const float *tmp = x; x = w; w = tmp;
    }
    float *out = (float *)d_out;
    float *out_idxf = out + 2 * (size_t)NPIX * CDIM;

    cudaFuncSetAttribute(mma_kernel, cudaFuncAttributeMaxDynamicSharedMemorySize, SMEM_MMA);

    prep_w<<<128, 256>>>(w);
    mma_kernel<<<512, 256, SMEM_MMA>>>(x, out_idxf);
    rescore2<<<512, 256>>>(w, out_idxf);
    gather_kernel<<<dim3(8, 64), 256>>>(x, w, out);
}

// round 14
// speedup vs baseline: 2.8201x; 1.1006x over previous
#include <cuda_runtime.h>
#include <cuda_fp16.h>
#include <cstdint>

#define CODES 1024
#define CDIM  256
#define HW    1024
#define NPIX  65536
#define NCHUNK 8            // 1024 codes / 128
#define NTILE  512          // 65536 px / 128

// ---------------- static scratch ----------------
__device__ __align__(1024) unsigned char g_wb[NCHUNK * 65536]; // fp16 B images (swizzled)
__device__ __align__(1024) float g_xT[(size_t)NPIX * CDIM];    // fp32 x, pixel-major (64MB)
__device__ float g_wsq[CODES];
__device__ float g_pmax[128];
__device__ float g_xx[NPIX];
__device__ int   g_cand[NPIX * 32];
__device__ float g_cs[NPIX * 32];      // approx score per candidate
__device__ int   g_cnt[NPIX];
__device__ int   g_idx[NPIX];
__device__ int   g_queue[NPIX];
__device__ int   g_qcnt;

// ---------------- helpers ----------------
__device__ __forceinline__ uint32_t smem_u32(const void *p) {
    uint32_t a;
    asm("{ .reg .u64 t; cvta.to.shared.u64 t, %1; cvt.u32.u64 %0, t; }" : "=r"(a) : "l"(p));
    return a;
}
__device__ __forceinline__ void cp16(uint32_t dst, const void *src) {
    asm volatile("cp.async.cg.shared.global [%0], [%1], 16;" :: "r"(dst), "l"(src) : "memory");
}
#define CP_COMMIT() asm volatile("cp.async.commit_group;" ::: "memory")
#define CP_WAIT1()  asm volatile("cp.async.wait_group 1;" ::: "memory")
#define CP_WAIT0()  asm volatile("cp.async.wait_group 0;" ::: "memory")

__device__ __forceinline__ uint32_t packh(float lo, float hi) {
    uint32_t r;
    asm("cvt.rn.f16x2.f32 %0, %1, %2;" : "=r"(r) : "f"(hi), "f"(lo));  // r = hi<<16 | lo
    return r;
}
// image layout: 128 rows x 256 fp16 k-major, rows of 512B = 32 16B-chunks,
// chunk swizzle: stored chunk index = chunk ^ (row & 7)  -> ldmatrix conflict-free
__device__ __forceinline__ uint32_t img_off(int row, int chunk) {
    return (uint32_t)row * 512u + (uint32_t)((chunk ^ (row & 7)) << 4);
}

__device__ __forceinline__ void ldsm_x4(uint32_t &r0, uint32_t &r1, uint32_t &r2, uint32_t &r3,
                                        uint32_t addr) {
    asm volatile("ldmatrix.sync.aligned.m8n8.x4.shared.b16 {%0,%1,%2,%3}, [%4];"
                 : "=r"(r0), "=r"(r1), "=r"(r2), "=r"(r3) : "r"(addr));
}
__device__ __forceinline__ void mma16816(float *d, uint32_t a0, uint32_t a1, uint32_t a2,
                                         uint32_t a3, uint32_t b0, uint32_t b1) {
    asm volatile("mma.sync.aligned.m16n8k16.row.col.f32.f16.f16.f32 "
                 "{%0,%1,%2,%3}, {%4,%5,%6,%7}, {%8,%9}, {%0,%1,%2,%3};"
                 : "+f"(d[0]), "+f"(d[1]), "+f"(d[2]), "+f"(d[3])
                 : "r"(a0), "r"(a1), "r"(a2), "r"(a3), "r"(b0), "r"(b1));
}

// =====================================================================
// prep_w: exact wsq, fp16 swizzled B images, per-block max|w|, zero queue
// grid 128 x 256 (8 codes/block, one warp per code)
// =====================================================================
__global__ void prep_w(const float *__restrict__ w) {
    __shared__ float wm[8];
    if (blockIdx.x == 0 && threadIdx.x == 0) g_qcnt = 0;
    int wid = threadIdx.x >> 5, lane = threadIdx.x & 31;
    int code = blockIdx.x * 8 + wid;
    const float *row = w + code * CDIM;
    float s = 0.f, pm = 0.f;
#pragma unroll
    for (int j = 0; j < 8; j++) {
        float v = row[lane + 32 * j];
        s = __fmaf_rn(v, v, s);
        pm = fmaxf(pm, fabsf(v));
    }
#pragma unroll
    for (int o = 16; o; o >>= 1) {
        s += __shfl_xor_sync(0xffffffffu, s, o);
        pm = fmaxf(pm, __shfl_xor_sync(0xffffffffu, pm, o));
    }
    if (lane == 0) { g_wsq[code] = s; wm[wid] = pm; }
    float f[8];
#pragma unroll
    for (int j = 0; j < 8; j++) f[j] = row[lane * 8 + j];
    uint4 v;
    v.x = packh(f[0], f[1]); v.y = packh(f[2], f[3]);
    v.z = packh(f[4], f[5]); v.w = packh(f[6], f[7]);
    int chunk = code >> 7, lr = code & 127;
    *(uint4 *)(g_wb + chunk * 65536 + img_off(lr, lane)) = v;
    __syncthreads();
    if (threadIdx.x == 0) {
        float m = 0.f;
        for (int i = 0; i < 8; i++) m = fmaxf(m, wm[i]);
        g_pmax[blockIdx.x] = m;
    }
}

// =====================================================================
// mma_kernel (fused prep_x): stages x fp32 in smem, computes exact stats,
//   converts fp16 A tile in-place, writes pixel-major g_xT (for rescore).
//   Warp tiling 4(px-groups of 32) x 2(N-halves of 64 codes).
//   Per ks: 2 A-LDSM + 4 B-LDSM + 16 MMA. Double-buffered B.
//   ONE syncthreads per chunk; tail refilters vs FINAL global min.
// grid 512 x 256
// =====================================================================
#define SM_WSQ 0
#define SM_CNT 4096
#define SM_RUN 5120
#define SM_XX  5632
#define SM_SX  6144
#define SM_A   8192
#define SM_B0  73728
#define SM_B1  139264
#define SM_STG 73728                       // fp32 staging overlays B0/B1
#define XSP    131
#define SMEM_MMA (SM_STG + 256 * XSP * 4)  // 207872

__device__ __forceinline__ void copy_img(uint32_t dst, const unsigned char *src, int tid) {
#pragma unroll
    for (int i = 0; i < 16; i++) {
        int c = tid + 256 * i;        // 4096 chunks of 16B
        cp16(dst + (uint32_t)c * 16u, src + (size_t)c * 16u);
    }
}

__global__ __launch_bounds__(256, 1) void mma_kernel(const float *__restrict__ x,
                                                     float *__restrict__ out_idxf) {
    extern __shared__ char smc[];
    uint32_t sb = smem_u32(smc);
    float *wsq_s = (float *)(smc + SM_WSQ);
    int *cnt_s = (int *)(smc + SM_CNT);
    int *run_s = (int *)(smc + SM_RUN);
    float *xx_s = (float *)(smc + SM_XX);
    float *sx_s = (float *)(smc + SM_SX);
    float *stg = (float *)(smc + SM_STG);
    const int tid = threadIdx.x, warp = tid >> 5, lane = tid & 31;
    const int tile = blockIdx.x;
    const int b = tile >> 3, hw0 = (tile & 7) * 128;
    const int wM = warp & 3;        // pixel group: 32 px
    const int wN = warp >> 2;       // code half: 64 codes
    const int m0 = wM * 32;

    // ---- stage x tile fp32 (coalesced k-major loads) ----
    {
        const float *src = x + (size_t)b * CDIM * HW + hw0;
#pragma unroll
        for (int it = 0; it < 128; it++) {
            int idx = tid + 256 * it;
            int kk = idx >> 7, p = idx & 127;
            stg[kk * XSP + p] = src[(size_t)kk * HW + p];
        }
    }
    for (int i = tid; i < CODES; i += 256) wsq_s[i] = g_wsq[i];
    if (tid < 128) {
        cnt_s[tid] = 0;
        run_s[tid] = 0x7f800000;           // +inf
    }
    if (tid == 0) {
        float m = 0.f;
        for (int i = 0; i < 128; i++) m = fmaxf(m, g_pmax[i]);
        ((float *)(smc + SM_CNT))[130] = m;
    }
    __syncthreads();

    // ---- exact sequential stats (identical op order to old prep_x) ----
    if (tid < 128) {
        float xxa = 0.f, sxa = 0.f;
        for (int kk = 0; kk < 256; kk++) {
            float v = stg[kk * XSP + tid];
            xxa = __fadd_rn(xxa, __fmul_rn(v, v));
            sxa = __fadd_rn(sxa, fabsf(v));
        }
        xx_s[tid] = xxa;
        sx_s[tid] = sxa;
        g_xx[tile * 128 + tid] = xxa;
    }
    // ---- convert to fp16 swizzled A tile ----
    {
        int p = tid & 127;
#pragma unroll
        for (int it = 0; it < 16; it++) {
            int oct = (tid >> 7) * 16 + it;          // 0..31
            float f[8];
#pragma unroll
            for (int j = 0; j < 8; j++) f[j] = stg[(oct * 8 + j) * XSP + p];
            uint4 v;
            v.x = packh(f[0], f[1]); v.y = packh(f[2], f[3]);
            v.z = packh(f[4], f[5]); v.w = packh(f[6], f[7]);
            *(uint4 *)(smc + SM_A + img_off(p, oct)) = v;
        }
    }
    // ---- write pixel-major fp32 g_xT (coalesced float4) ----
    {
        float *xtd = g_xT + (size_t)tile * 128 * CDIM;
        int k4 = tid & 63;                  // 64 float4 per pixel
        for (int pp = tid >> 6; pp < 128; pp += 4) {
            float4 v4;
            v4.x = stg[(k4 * 4 + 0) * XSP + pp];
            v4.y = stg[(k4 * 4 + 1) * XSP + pp];
            v4.z = stg[(k4 * 4 + 2) * XSP + pp];
            v4.w = stg[(k4 * 4 + 3) * XSP + pp];
            *(float4 *)(xtd + (size_t)pp * CDIM + k4 * 4) = v4;
        }
    }
    __syncthreads();   // staging reads done -> B prefetch may overwrite

    const float wmax = ((float *)(smc + SM_CNT))[130];

    // first B chunk prefetch
    copy_img(sb + SM_B0, g_wb, tid);
    CP_COMMIT();

    // 4 pixel rows per thread: [f][r] = m0 + f*16 + r*8 + (lane>>2)
    const int pr = lane >> 2;
    float xxv[2][2], THv[2][2];
#pragma unroll
    for (int f = 0; f < 2; f++)
#pragma unroll
        for (int r = 0; r < 2; r++) {
            int pxl = m0 + f * 16 + r * 8 + pr;
            xxv[f][r] = xx_s[pxl];
            THv[f][r] = __fmaf_rn(sx_s[pxl] * wmax, 0.006f, 4e-4f);   // fp16 bound, 1.5x safety
        }

    // ldmatrix addressing
    const int mat = lane >> 3, r7 = lane & 7;
    const int a_row0 = m0 + r7 + ((mat & 1) << 3);
    const int a_cadd = mat >> 1;
    const uint32_t a_base0 = sb + SM_A + (uint32_t)a_row0 * 512u;       // f=0
    const uint32_t a_base1 = a_base0 + 16u * 512u;                      // f=1
    const int b_rowoff = r7 + ((mat >> 1) << 3);
    const int b_cadd = mat & 1;
    const uint32_t b_roff = (uint32_t)(wN * 64) * 512u + (uint32_t)b_rowoff * 512u;

    for (int c = 0; c < NCHUNK; c++) {
        if (c < 7) {
            copy_img(sb + (((c + 1) & 1) ? SM_B1 : SM_B0), g_wb + (size_t)(c + 1) * 65536, tid);
            CP_COMMIT();
            CP_WAIT1();
        } else {
            CP_WAIT0();
        }
        __syncthreads();   // buffer guard + makes prev-chunk atomicMins visible

        const uint32_t b_base = sb + ((c & 1) ? SM_B1 : SM_B0) + b_roff;

        float acc[2][8][4];
#pragma unroll
        for (int f = 0; f < 2; f++)
#pragma unroll
            for (int nb = 0; nb < 8; nb++)
#pragma unroll
                for (int j = 0; j < 4; j++) acc[f][nb][j] = 0.f;

#pragma unroll
        for (int ks = 0; ks < 16; ks++) {
            const uint32_t koff = (uint32_t)(((2 * ks + a_cadd) ^ r7) << 4);
            const uint32_t koffb = (uint32_t)(((2 * ks + b_cadd) ^ r7) << 4);
            uint32_t a00, a01, a02, a03, a10, a11, a12, a13;
            ldsm_x4(a00, a01, a02, a03, a_base0 + koff);
            ldsm_x4(a10, a11, a12, a13, a_base1 + koff);
#pragma unroll
            for (int g = 0; g < 4; g++) {
                uint32_t b0, b1, b2, b3;
                ldsm_x4(b0, b1, b2, b3, b_base + (uint32_t)(g * 8192) + koffb);
                mma16816(acc[0][2 * g],     a00, a01, a02, a03, b0, b1);
                mma16816(acc[0][2 * g + 1], a00, a01, a02, a03, b2, b3);
                mma16816(acc[1][2 * g],     a10, a11, a12, a13, b0, b1);
                mma16816(acc[1][2 * g + 1], a10, a11, a12, a13, b2, b3);
            }
        }

        // ---- epilogue: scores, quad-min, push vs min(stale-global, warpmin) ----
        const int ncol = 2 * (lane & 3);
        const int code0 = c * 128 + wN * 64 + ncol;
        float lm[2][2];
        lm[0][0] = lm[0][1] = lm[1][0] = lm[1][1] = __int_as_float(0x7f800000);
#pragma unroll
        for (int f = 0; f < 2; f++)
#pragma unroll
            for (int nb = 0; nb < 8; nb++) {
                const float *wq = wsq_s + c * 128 + wN * 64 + nb * 8 + ncol;
                float s;
                s = __fadd_rn(__fmaf_rn(-2.f, acc[f][nb][0], xxv[f][0]), wq[0]); acc[f][nb][0] = s; lm[f][0] = fminf(lm[f][0], s);
                s = __fadd_rn(__fmaf_rn(-2.f, acc[f][nb][1], xxv[f][0]), wq[1]); acc[f][nb][1] = s; lm[f][0] = fminf(lm[f][0], s);
                s = __fadd_rn(__fmaf_rn(-2.f, acc[f][nb][2], xxv[f][1]), wq[0]); acc[f][nb][2] = s; lm[f][1] = fminf(lm[f][1], s);
                s = __fadd_rn(__fmaf_rn(-2.f, acc[f][nb][3], xxv[f][1]), wq[1]); acc[f][nb][3] = s; lm[f][1] = fminf(lm[f][1], s);
            }
#pragma unroll
        for (int o = 1; o <= 2; o <<= 1)
#pragma unroll
            for (int f = 0; f < 2; f++)
#pragma unroll
                for (int r = 0; r < 2; r++)
                    lm[f][r] = fminf(lm[f][r], __shfl_xor_sync(0xffffffffu, lm[f][r], o));

#pragma unroll
        for (int f = 0; f < 2; f++)
#pragma unroll
            for (int r = 0; r < 2; r++) {
                const int pxl = m0 + f * 16 + r * 8 + pr;
                const int pix = tile * 128 + pxl;
                const float th = fminf(__int_as_float(run_s[pxl]), lm[f][r]) + THv[f][r];
#pragma unroll
                for (int nb = 0; nb < 8; nb++) {
                    int cb = code0 + nb * 8;
                    float s0 = acc[f][nb][2 * r], s1 = acc[f][nb][2 * r + 1];
                    if (s0 <= th) {
                        int sl = atomicAdd(&cnt_s[pxl], 1);
                        if (sl < 32) {
                            g_cand[(size_t)pix * 32 + sl] = cb;
                            g_cs[(size_t)pix * 32 + sl] = s0;
                        }
                    }
                    if (s1 <= th) {
                        int sl = atomicAdd(&cnt_s[pxl], 1);
                        if (sl < 32) {
                            g_cand[(size_t)pix * 32 + sl] = cb + 1;
                            g_cs[(size_t)pix * 32 + sl] = s1;
                        }
                    }
                }
            }
        if ((lane & 3) == 0) {
#pragma unroll
            for (int f = 0; f < 2; f++)
#pragma unroll
                for (int r = 0; r < 2; r++)
                    atomicMin(&run_s[m0 + f * 16 + r * 8 + pr], __float_as_int(lm[f][r]));
        }
    }
    __syncthreads();   // final runmin + counters visible

    // ---- tail: refilter candidates against FINAL runmin, finalize or queue ----
    if (tid < 128) {
        int pix = tile * 128 + tid;
        int cnt = cnt_s[tid];
        if (cnt > 32) {
            g_cnt[pix] = cnt;                       // overflow -> full-scan path
            int q = atomicAdd(&g_qcnt, 1);
            g_queue[q] = pix;
        } else {
            const float th = __int_as_float(run_s[tid]) +
                             __fmaf_rn(sx_s[tid] * wmax, 0.006f, 4e-4f);
            int nk = 0, first = 0;
            for (int j = 0; j < cnt; j++) {
                int code = g_cand[(size_t)pix * 32 + j];
                float s = g_cs[(size_t)pix * 32 + j];
                if (s <= th) {
                    g_cand[(size_t)pix * 32 + nk] = code;   // in-place compact (nk<=j)
                    if (nk == 0) first = code;
                    nk++;
                }
            }
            g_cnt[pix] = nk;
            if (nk == 1) {
                g_idx[pix] = first;
                out_idxf[pix] = (float)first;
            } else {
                int q = atomicAdd(&g_qcnt, 1);
                g_queue[q] = pix;
            }
        }
    }
}

// =====================================================================
// rescore2: 4 pixels per warp, 8 lanes per pixel; one candidate per lane
//   stride 8. Exact fp32 chain (sequential ascending k). x from g_xT.
// grid 512 x 256
// =====================================================================
__global__ __launch_bounds__(256) void rescore2(const float *__restrict__ w,
                                                float *__restrict__ out_idxf) {
    const int lane = threadIdx.x & 31;
    const int sg = lane >> 3;            // subgroup 0..3 (pixel slot)
    const int lid8 = lane & 7;
    const int gwarp = (blockIdx.x * blockDim.x + threadIdx.x) >> 5;
    const int nwarp = (gridDim.x * blockDim.x) >> 5;
    const int total = g_qcnt;
    const float INF = __int_as_float(0x7f800000);

    for (int qb = gwarp * 4; qb < total; qb += nwarp * 4) {
        int q = qb + sg;
        bool valid = (q < total);
        int pix = 0, cnt = 0;
        float xxp = 0.f;
        if (valid) {
            pix = g_queue[q];
            cnt = g_cnt[pix];
            xxp = g_xx[pix];
        }
        const float4 *xb4 = (const float4 *)(g_xT + (size_t)pix * CDIM);

        float bestd = INF;
        int besti = CODES;
        int scanN = (cnt > 32) ? CODES : cnt;   // overflow -> full scan

        for (int t = lid8; t < scanN; t += 8) {
            int cidx = (cnt > 32) ? t : g_cand[(size_t)pix * 32 + t];
            const float4 *wr = (const float4 *)(w + (size_t)cidx * CDIM);
            float dot = 0.f;
#pragma unroll 8
            for (int qq = 0; qq < 64; qq++) {
                float4 wv = wr[qq];
                float4 xv = xb4[qq];
                dot = __fmaf_rn(xv.x, wv.x, dot);
                dot = __fmaf_rn(xv.y, wv.y, dot);
                dot = __fmaf_rn(xv.z, wv.z, dot);
                dot = __fmaf_rn(xv.w, wv.w, dot);
            }
            float d = __fadd_rn(__fmaf_rn(-2.f, dot, xxp), g_wsq[cidx]);
            if (d < bestd || (d == bestd && cidx < besti)) { bestd = d; besti = cidx; }
        }
        // reduce across the 8 lanes of this subgroup (xor offsets stay in-group)
#pragma unroll
        for (int o = 1; o <= 4; o <<= 1) {
            float od = __shfl_xor_sync(0xffffffffu, bestd, o);
            int   oi = __shfl_xor_sync(0xffffffffu, besti, o);
            if (od < bestd || (od == bestd && oi < besti)) { bestd = od; besti = oi; }
        }
        if (valid && lid8 == 0) {
            g_idx[pix] = besti;
            out_idxf[pix] = (float)besti;
        }
    }
}

// =====================================================================
// gather: quantized = weight[idx], ste = (q - x) + x
//   Thread-per-pixel contiguous w-row reads -> smem transpose ->
//   FLOAT4 coalesced loads/stores (pixel quads).
//   grid (8, 64) x 256, 4 sub-iterations of 256 pixels.
// =====================================================================
#define QS 260
__global__ __launch_bounds__(256)
void gather_kernel(const float *__restrict__ x, const float *__restrict__ w,
                   float *__restrict__ out) {
    __shared__ float qsm[32 * QS];
    const int b = blockIdx.y;
    const int c0 = blockIdx.x * 32;
    const int tid = threadIdx.x;
    const int tq = tid & 63;          // pixel quad: pixels 4*tq..4*tq+3
    const int cg = tid >> 6;          // channel group 0..3

    const float *xb = x + (size_t)b * CDIM * HW;
    float *qo = out + (size_t)b * CDIM * HW;
    float *so = out + (size_t)NPIX * CDIM + (size_t)b * CDIM * HW;

    for (int sub = 0; sub < 4; sub++) {
        const int px = sub * 256 + tid;
        int row = g_idx[b * HW + px];
        const float4 *wr = (const float4 *)(w + (size_t)row * CDIM + c0);
#pragma unroll
        for (int j = 0; j < 8; j++) {
            float4 v = wr[j];
            qsm[(4 * j + 0) * QS + tid] = v.x;
            qsm[(4 * j + 1) * QS + tid] = v.y;
            qsm[(4 * j + 2) * QS + tid] = v.z;
            qsm[(4 * j + 3) * QS + tid] = v.w;
        }
        __syncthreads();
#pragma unroll
        for (int i = 0; i < 8; i++) {
            int c = cg + 4 * i;       // 0..31
            size_t off = (size_t)(c0 + c) * HW + sub * 256 + 4 * tq;
            float4 qv = *(const float4 *)(qsm + c * QS + 4 * tq);
            float4 xv = *(const float4 *)(xb + off);
            *(float4 *)(qo + off) = qv;
            float4 sv;
            sv.x = __fadd_rn(__fsub_rn(qv.x, xv.x), xv.x);
            sv.y = __fadd_rn(__fsub_rn(qv.y, xv.y), xv.y);
            sv.z = __fadd_rn(__fsub_rn(qv.z, xv.z), xv.z);
            sv.w = __fadd_rn(__fsub_rn(qv.w, xv.w), xv.w);
            *(float4 *)(so + off) = sv;
        }
        __syncthreads();
    }
}

// =====================================================================
extern "C" void kernel_launch(void *const *d_in, const int *in_sizes, int n_in,
                              void *d_out, int out_size) {
    const float *x = (const float *)d_in[0];
    const float *w = (const float *)d_in[1];
    if (n_in >= 2 && in_sizes[0] == CODES * CDIM && in_sizes[1] == NPIX * CDIM) {
        const float *tmp = x; x = w; w = tmp;
    }
    float *out = (float *)d_out;
    float *out_idxf = out + 2 * (size_t)NPIX * CDIM;

    cudaFuncSetAttribute(mma_kernel, cudaFuncAttributeMaxDynamicSharedMemorySize, SMEM_MMA);

    prep_w<<<128, 256>>>(w);
    mma_kernel<<<512, 256, SMEM_MMA>>>(x, out_idxf);
    rescore2<<<512, 256>>>(w, out_idxf);
    gather_kernel<<<dim3(8, 64), 256>>>(x, w, out);
}

// round 15
// speedup vs baseline: 2.8223x; 1.0008x over previous
#include <cuda_runtime.h>
#include <cuda_fp16.h>
#include <cstdint>

#define CODES 1024
#define CDIM  256
#define HW    1024
#define NPIX  65536
#define NCHUNK 8            // 1024 codes / 128
#define NTILE  512          // 65536 px / 128

// ---------------- static scratch ----------------
__device__ __align__(1024) unsigned char g_wb[NCHUNK * 65536]; // fp16 B images (swizzled)
__device__ __align__(1024) float g_xT[(size_t)NPIX * CDIM];    // fp32 x, pixel-major (64MB)
__device__ float g_wsq[CODES];
__device__ float g_pmax[128];
__device__ float g_xx[NPIX];
__device__ int   g_cand[NPIX * 32];
__device__ float g_cs[NPIX * 32];      // approx score per candidate
__device__ int   g_cnt[NPIX];
__device__ int   g_idx[NPIX];
__device__ int   g_queue[NPIX];
__device__ int   g_qcnt;

// ---------------- helpers ----------------
__device__ __forceinline__ uint32_t smem_u32(const void *p) {
    uint32_t a;
    asm("{ .reg .u64 t; cvta.to.shared.u64 t, %1; cvt.u32.u64 %0, t; }" : "=r"(a) : "l"(p));
    return a;
}
__device__ __forceinline__ void cp16(uint32_t dst, const void *src) {
    asm volatile("cp.async.cg.shared.global [%0], [%1], 16;" :: "r"(dst), "l"(src) : "memory");
}
#define CP_COMMIT() asm volatile("cp.async.commit_group;" ::: "memory")
#define CP_WAIT1()  asm volatile("cp.async.wait_group 1;" ::: "memory")
#define CP_WAIT0()  asm volatile("cp.async.wait_group 0;" ::: "memory")

__device__ __forceinline__ uint32_t packh(float lo, float hi) {
    uint32_t r;
    asm("cvt.rn.f16x2.f32 %0, %1, %2;" : "=r"(r) : "f"(hi), "f"(lo));  // r = hi<<16 | lo
    return r;
}
// image layout: 128 rows x 256 fp16 k-major, rows of 512B = 32 16B-chunks,
// chunk swizzle: stored chunk index = chunk ^ (row & 7)  -> ldmatrix conflict-free
__device__ __forceinline__ uint32_t img_off(int row, int chunk) {
    return (uint32_t)row * 512u + (uint32_t)((chunk ^ (row & 7)) << 4);
}

__device__ __forceinline__ void ldsm_x4(uint32_t &r0, uint32_t &r1, uint32_t &r2, uint32_t &r3,
                                        uint32_t addr) {
    asm volatile("ldmatrix.sync.aligned.m8n8.x4.shared.b16 {%0,%1,%2,%3}, [%4];"
                 : "=r"(r0), "=r"(r1), "=r"(r2), "=r"(r3) : "r"(addr));
}
__device__ __forceinline__ void mma16816(float *d, uint32_t a0, uint32_t a1, uint32_t a2,
                                         uint32_t a3, uint32_t b0, uint32_t b1) {
    asm volatile("mma.sync.aligned.m16n8k16.row.col.f32.f16.f16.f32 "
                 "{%0,%1,%2,%3}, {%4,%5,%6,%7}, {%8,%9}, {%0,%1,%2,%3};"
                 : "+f"(d[0]), "+f"(d[1]), "+f"(d[2]), "+f"(d[3])
                 : "r"(a0), "r"(a1), "r"(a2), "r"(a3), "r"(b0), "r"(b1));
}

// =====================================================================
// prep_w: exact wsq, fp16 swizzled B images, per-block max|w|, zero queue
// grid 128 x 256 (8 codes/block, one warp per code)
// =====================================================================
__global__ void prep_w(const float *__restrict__ w) {
    __shared__ float wm[8];
    if (blockIdx.x == 0 && threadIdx.x == 0) g_qcnt = 0;
    int wid = threadIdx.x >> 5, lane = threadIdx.x & 31;
    int code = blockIdx.x * 8 + wid;
    const float *row = w + code * CDIM;
    float s = 0.f, pm = 0.f;
#pragma unroll
    for (int j = 0; j < 8; j++) {
        float v = row[lane + 32 * j];
        s = __fmaf_rn(v, v, s);
        pm = fmaxf(pm, fabsf(v));
    }
#pragma unroll
    for (int o = 16; o; o >>= 1) {
        s += __shfl_xor_sync(0xffffffffu, s, o);
        pm = fmaxf(pm, __shfl_xor_sync(0xffffffffu, pm, o));
    }
    if (lane == 0) { g_wsq[code] = s; wm[wid] = pm; }
    float f[8];
#pragma unroll
    for (int j = 0; j < 8; j++) f[j] = row[lane * 8 + j];
    uint4 v;
    v.x = packh(f[0], f[1]); v.y = packh(f[2], f[3]);
    v.z = packh(f[4], f[5]); v.w = packh(f[6], f[7]);
    int chunk = code >> 7, lr = code & 127;
    *(uint4 *)(g_wb + chunk * 65536 + img_off(lr, lane)) = v;
    __syncthreads();
    if (threadIdx.x == 0) {
        float m = 0.f;
        for (int i = 0; i < 8; i++) m = fmaxf(m, wm[i]);
        g_pmax[blockIdx.x] = m;
    }
}

// =====================================================================
// mma_kernel (fused prep_x, 2-half prologue): B0 cp.async issued FIRST and
//   overlaps the prologue (staging overlays only the B1 region).
//   Staging uses LDG.128. Stats keep the exact sequential ascending-k order.
//   Warp tiling 4(px-groups of 32) x 2(N-halves of 64 codes).
//   Per ks: 2 A-LDSM + 4 B-LDSM + 16 MMA. Double-buffered B.
//   ONE syncthreads per chunk; tail refilters vs FINAL global min.
// grid 512 x 256
// =====================================================================
#define SM_WSQ 0
#define SM_CNT 4096
#define SM_RUN 5120
#define SM_XX  5632
#define SM_SX  6144
#define SM_A   8192
#define SM_B0  73728
#define SM_B1  139264
#define SM_STG 139264                      // fp32 half-staging overlays B1 only
#define XSP    131
#define SMEM_MMA (SM_STG + 128 * XSP * 4)  // 206336

__device__ __forceinline__ void copy_img(uint32_t dst, const unsigned char *src, int tid) {
#pragma unroll
    for (int i = 0; i < 16; i++) {
        int c = tid + 256 * i;        // 4096 chunks of 16B
        cp16(dst + (uint32_t)c * 16u, src + (size_t)c * 16u);
    }
}

__global__ __launch_bounds__(256, 1) void mma_kernel(const float *__restrict__ x,
                                                     float *__restrict__ out_idxf) {
    extern __shared__ char smc[];
    uint32_t sb = smem_u32(smc);
    float *wsq_s = (float *)(smc + SM_WSQ);
    int *cnt_s = (int *)(smc + SM_CNT);
    int *run_s = (int *)(smc + SM_RUN);
    float *xx_s = (float *)(smc + SM_XX);
    float *sx_s = (float *)(smc + SM_SX);
    float *stg = (float *)(smc + SM_STG);
    const int tid = threadIdx.x, warp = tid >> 5, lane = tid & 31;
    const int tile = blockIdx.x;
    const int b = tile >> 3, hw0 = (tile & 7) * 128;
    const int wM = warp & 3;        // pixel group: 32 px
    const int wN = warp >> 2;       // code half: 64 codes
    const int m0 = wM * 32;

    // ---- B0 prefetch FIRST: overlaps the whole prologue ----
    copy_img(sb + SM_B0, g_wb, tid);
    CP_COMMIT();

    for (int i = tid; i < CODES; i += 256) wsq_s[i] = g_wsq[i];
    if (tid < 128) {
        cnt_s[tid] = 0;
        run_s[tid] = 0x7f800000;           // +inf
    }
    if (tid == 0) {
        float m = 0.f;
        for (int i = 0; i < 128; i++) m = fmaxf(m, g_pmax[i]);
        ((float *)(smc + SM_CNT))[130] = m;
    }

    // ---- prologue in two 128-k halves (staging overlays B1 only) ----
    float xxa = 0.f, sxa = 0.f;            // persists across halves (tid<128)
    float *xtd = g_xT + (size_t)tile * 128 * CDIM;
    for (int h = 0; h < 2; h++) {
        const float *src = x + (size_t)b * CDIM * HW + (size_t)(h * 128) * HW + hw0;
        // LDG.128 staging: 4096 float4, 16 per thread
#pragma unroll
        for (int i = 0; i < 16; i++) {
            int idx = tid + 256 * i;          // 0..4095
            int kk = idx >> 5, q = idx & 31;  // kk 0..127, q = float4 col
            float4 v = *(const float4 *)(src + (size_t)kk * HW + 4 * q);
            float *d = stg + kk * XSP + 4 * q;
            d[0] = v.x; d[1] = v.y; d[2] = v.z; d[3] = v.w;
        }
        __syncthreads();
        // exact sequential stats (ascending k; identical op order)
        if (tid < 128) {
            for (int kk = 0; kk < 128; kk++) {
                float v = stg[kk * XSP + tid];
                xxa = __fadd_rn(xxa, __fmul_rn(v, v));
                sxa = __fadd_rn(sxa, fabsf(v));
            }
        }
        // convert to fp16 swizzled A tile (chunks h*16 .. h*16+15)
        {
            int p = tid & 127;
#pragma unroll
            for (int it = 0; it < 8; it++) {
                int oc = (tid >> 7) * 8 + it;        // local oct 0..15
                float f[8];
#pragma unroll
                for (int j = 0; j < 8; j++) f[j] = stg[(oc * 8 + j) * XSP + p];
                uint4 v;
                v.x = packh(f[0], f[1]); v.y = packh(f[2], f[3]);
                v.z = packh(f[4], f[5]); v.w = packh(f[6], f[7]);
                *(uint4 *)(smc + SM_A + img_off(p, h * 16 + oc)) = v;
            }
        }
        // pixel-major fp32 g_xT columns h*128..h*128+127
        {
            int k4 = tid & 31;                  // 32 float4 per half
            for (int pp = tid >> 5; pp < 128; pp += 8) {
                float4 v4;
                v4.x = stg[(k4 * 4 + 0) * XSP + pp];
                v4.y = stg[(k4 * 4 + 1) * XSP + pp];
                v4.z = stg[(k4 * 4 + 2) * XSP + pp];
                v4.w = stg[(k4 * 4 + 3) * XSP + pp];
                *(float4 *)(xtd + (size_t)pp * CDIM + h * 128 + k4 * 4) = v4;
            }
        }
        __syncthreads();   // stg consumed -> next half (or B1 prefetch) may overwrite
    }
    if (tid < 128) {
        xx_s[tid] = xxa;
        sx_s[tid] = sxa;
        g_xx[tile * 128 + tid] = xxa;
    }
    __syncthreads();

    const float wmax = ((float *)(smc + SM_CNT))[130];

    // 4 pixel rows per thread: [f][r] = m0 + f*16 + r*8 + (lane>>2)
    const int pr = lane >> 2;
    float xxv[2][2], THv[2][2];
#pragma unroll
    for (int f = 0; f < 2; f++)
#pragma unroll
        for (int r = 0; r < 2; r++) {
            int pxl = m0 + f * 16 + r * 8 + pr;
            xxv[f][r] = xx_s[pxl];
            THv[f][r] = __fmaf_rn(sx_s[pxl] * wmax, 0.006f, 4e-4f);   // fp16 bound, 1.5x safety
        }

    // ldmatrix addressing
    const int mat = lane >> 3, r7 = lane & 7;
    const int a_row0 = m0 + r7 + ((mat & 1) << 3);
    const int a_cadd = mat >> 1;
    const uint32_t a_base0 = sb + SM_A + (uint32_t)a_row0 * 512u;       // f=0
    const uint32_t a_base1 = a_base0 + 16u * 512u;                      // f=1
    const int b_rowoff = r7 + ((mat >> 1) << 3);
    const int b_cadd = mat & 1;
    const uint32_t b_roff = (uint32_t)(wN * 64) * 512u + (uint32_t)b_rowoff * 512u;

    for (int c = 0; c < NCHUNK; c++) {
        if (c < 7) {
            copy_img(sb + (((c + 1) & 1) ? SM_B1 : SM_B0), g_wb + (size_t)(c + 1) * 65536, tid);
            CP_COMMIT();
            CP_WAIT1();
        } else {
            CP_WAIT0();
        }
        __syncthreads();   // buffer guard + makes prev-chunk atomicMins visible

        const uint32_t b_base = sb + ((c & 1) ? SM_B1 : SM_B0) + b_roff;

        float acc[2][8][4];
#pragma unroll
        for (int f = 0; f < 2; f++)
#pragma unroll
            for (int nb = 0; nb < 8; nb++)
#pragma unroll
                for (int j = 0; j < 4; j++) acc[f][nb][j] = 0.f;

#pragma unroll
        for (int ks = 0; ks < 16; ks++) {
            const uint32_t koff = (uint32_t)(((2 * ks + a_cadd) ^ r7) << 4);
            const uint32_t koffb = (uint32_t)(((2 * ks + b_cadd) ^ r7) << 4);
            uint32_t a00, a01, a02, a03, a10, a11, a12, a13;
            ldsm_x4(a00, a01, a02, a03, a_base0 + koff);
            ldsm_x4(a10, a11, a12, a13, a_base1 + koff);
#pragma unroll
            for (int g = 0; g < 4; g++) {
                uint32_t b0, b1, b2, b3;
                ldsm_x4(b0, b1, b2, b3, b_base + (uint32_t)(g * 8192) + koffb);
                mma16816(acc[0][2 * g],     a00, a01, a02, a03, b0, b1);
                mma16816(acc[0][2 * g + 1], a00, a01, a02, a03, b2, b3);
                mma16816(acc[1][2 * g],     a10, a11, a12, a13, b0, b1);
                mma16816(acc[1][2 * g + 1], a10, a11, a12, a13, b2, b3);
            }
        }

        // ---- epilogue: scores, quad-min, push vs min(stale-global, warpmin) ----
        const int ncol = 2 * (lane & 3);
        const int code0 = c * 128 + wN * 64 + ncol;
        float lm[2][2];
        lm[0][0] = lm[0][1] = lm[1][0] = lm[1][1] = __int_as_float(0x7f800000);
#pragma unroll
        for (int f = 0; f < 2; f++)
#pragma unroll
            for (int nb = 0; nb < 8; nb++) {
                const float *wq = wsq_s + c * 128 + wN * 64 + nb * 8 + ncol;
                float s;
                s = __fadd_rn(__fmaf_rn(-2.f, acc[f][nb][0], xxv[f][0]), wq[0]); acc[f][nb][0] = s; lm[f][0] = fminf(lm[f][0], s);
                s = __fadd_rn(__fmaf_rn(-2.f, acc[f][nb][1], xxv[f][0]), wq[1]); acc[f][nb][1] = s; lm[f][0] = fminf(lm[f][0], s);
                s = __fadd_rn(__fmaf_rn(-2.f, acc[f][nb][2], xxv[f][1]), wq[0]); acc[f][nb][2] = s; lm[f][1] = fminf(lm[f][1], s);
                s = __fadd_rn(__fmaf_rn(-2.f, acc[f][nb][3], xxv[f][1]), wq[1]); acc[f][nb][3] = s; lm[f][1] = fminf(lm[f][1], s);
            }
#pragma unroll
        for (int o = 1; o <= 2; o <<= 1)
#pragma unroll
            for (int f = 0; f < 2; f++)
#pragma unroll
                for (int r = 0; r < 2; r++)
                    lm[f][r] = fminf(lm[f][r], __shfl_xor_sync(0xffffffffu, lm[f][r], o));

#pragma unroll
        for (int f = 0; f < 2; f++)
#pragma unroll
            for (int r = 0; r < 2; r++) {
                const int pxl = m0 + f * 16 + r * 8 + pr;
                const int pix = tile * 128 + pxl;
                const float th = fminf(__int_as_float(run_s[pxl]), lm[f][r]) + THv[f][r];
#pragma unroll
                for (int nb = 0; nb < 8; nb++) {
                    int cb = code0 + nb * 8;
                    float s0 = acc[f][nb][2 * r], s1 = acc[f][nb][2 * r + 1];
                    if (s0 <= th) {
                        int sl = atomicAdd(&cnt_s[pxl], 1);
                        if (sl < 32) {
                            g_cand[(size_t)pix * 32 + sl] = cb;
                            g_cs[(size_t)pix * 32 + sl] = s0;
                        }
                    }
                    if (s1 <= th) {
                        int sl = atomicAdd(&cnt_s[pxl], 1);
                        if (sl < 32) {
                            g_cand[(size_t)pix * 32 + sl] = cb + 1;
                            g_cs[(size_t)pix * 32 + sl] = s1;
                        }
                    }
                }
            }
        if ((lane & 3) == 0) {
#pragma unroll
            for (int f = 0; f < 2; f++)
#pragma unroll
                for (int r = 0; r < 2; r++)
                    atomicMin(&run_s[m0 + f * 16 + r * 8 + pr], __float_as_int(lm[f][r]));
        }
    }
    __syncthreads();   // final runmin + counters visible

    // ---- tail: refilter candidates against FINAL runmin, finalize or queue ----
    if (tid < 128) {
        int pix = tile * 128 + tid;
        int cnt = cnt_s[tid];
        if (cnt > 32) {
            g_cnt[pix] = cnt;                       // overflow -> full-scan path
            int q = atomicAdd(&g_qcnt, 1);
            g_queue[q] = pix;
        } else {
            const float th = __int_as_float(run_s[tid]) +
                             __fmaf_rn(sx_s[tid] * wmax, 0.006f, 4e-4f);
            int nk = 0, first = 0;
            for (int j = 0; j < cnt; j++) {
                int code = g_cand[(size_t)pix * 32 + j];
                float s = g_cs[(size_t)pix * 32 + j];
                if (s <= th) {
                    g_cand[(size_t)pix * 32 + nk] = code;   // in-place compact (nk<=j)
                    if (nk == 0) first = code;
                    nk++;
                }
            }
            g_cnt[pix] = nk;
            if (nk == 1) {
                g_idx[pix] = first;
                out_idxf[pix] = (float)first;
            } else {
                int q = atomicAdd(&g_qcnt, 1);
                g_queue[q] = pix;
            }
        }
    }
}

// =====================================================================
// rescore2: 4 pixels per warp, 8 lanes per pixel; one candidate per lane
//   stride 8. Exact fp32 chain (sequential ascending k). x from g_xT.
// grid 1024 x 256
// =====================================================================
__global__ __launch_bounds__(256) void rescore2(const float *__restrict__ w,
                                                float *__restrict__ out_idxf) {
    const int lane = threadIdx.x & 31;
    const int sg = lane >> 3;            // subgroup 0..3 (pixel slot)
    const int lid8 = lane & 7;
    const int gwarp = (blockIdx.x * blockDim.x + threadIdx.x) >> 5;
    const int nwarp = (gridDim.x * blockDim.x) >> 5;
    const int total = g_qcnt;
    const float INF = __int_as_float(0x7f800000);

    for (int qb = gwarp * 4; qb < total; qb += nwarp * 4) {
        int q = qb + sg;
        bool valid = (q < total);
        int pix = 0, cnt = 0;
        float xxp = 0.f;
        if (valid) {
            pix = g_queue[q];
            cnt = g_cnt[pix];
            xxp = g_xx[pix];
        }
        const float4 *xb4 = (const float4 *)(g_xT + (size_t)pix * CDIM);

        float bestd = INF;
        int besti = CODES;
        int scanN = (cnt > 32) ? CODES : cnt;   // overflow -> full scan

        for (int t = lid8; t < scanN; t += 8) {
            int cidx = (cnt > 32) ? t : g_cand[(size_t)pix * 32 + t];
            const float4 *wr = (const float4 *)(w + (size_t)cidx * CDIM);
            float dot = 0.f;
#pragma unroll 8
            for (int qq = 0; qq < 64; qq++) {
                float4 wv = wr[qq];
                float4 xv = xb4[qq];
                dot = __fmaf_rn(xv.x, wv.x, dot);
                dot = __fmaf_rn(xv.y, wv.y, dot);
                dot = __fmaf_rn(xv.z, wv.z, dot);
                dot = __fmaf_rn(xv.w, wv.w, dot);
            }
            float d = __fadd_rn(__fmaf_rn(-2.f, dot, xxp), g_wsq[cidx]);
            if (d < bestd || (d == bestd && cidx < besti)) { bestd = d; besti = cidx; }
        }
        // reduce across the 8 lanes of this subgroup (xor offsets stay in-group)
#pragma unroll
        for (int o = 1; o <= 4; o <<= 1) {
            float od = __shfl_xor_sync(0xffffffffu, bestd, o);
            int   oi = __shfl_xor_sync(0xffffffffu, besti, o);
            if (od < bestd || (od == bestd && oi < besti)) { bestd = od; besti = oi; }
        }
        if (valid && lid8 == 0) {
            g_idx[pix] = besti;
            out_idxf[pix] = (float)besti;
        }
    }
}

// =====================================================================
// gather: quantized = weight[idx], ste = (q - x) + x
//   Thread-per-pixel contiguous w-row reads -> smem transpose ->
//   FLOAT4 coalesced loads/stores (pixel quads).
//   grid (16, 64) x 256 (16 channels/block), 4 sub-iterations of 256 px.
// =====================================================================
#define QS 260
__global__ __launch_bounds__(256)
void gather_kernel(const float *__restrict__ x, const float *__restrict__ w,
                   float *__restrict__ out) {
    __shared__ float qsm[16 * QS];
    const int b = blockIdx.y;
    const int c0 = blockIdx.x * 16;
    const int tid = threadIdx.x;
    const int tq = tid & 63;          // pixel quad: pixels 4*tq..4*tq+3
    const int cg = tid >> 6;          // channel group 0..3

    const float *xb = x + (size_t)b * CDIM * HW;
    float *qo = out + (size_t)b * CDIM * HW;
    float *so = out + (size_t)NPIX * CDIM + (size_t)b * CDIM * HW;

    for (int sub = 0; sub < 4; sub++) {
        const int px = sub * 256 + tid;
        int row = g_idx[b * HW + px];
        const float4 *wr = (const float4 *)(w + (size_t)row * CDIM + c0);
#pragma unroll
        for (int j = 0; j < 4; j++) {
            float4 v = wr[j];
            qsm[(4 * j + 0) * QS + tid] = v.x;
            qsm[(4 * j + 1) * QS + tid] = v.y;
            qsm[(4 * j + 2) * QS + tid] = v.z;
            qsm[(4 * j + 3) * QS + tid] = v.w;
        }
        __syncthreads();
#pragma unroll
        for (int i = 0; i < 4; i++) {
            int c = cg + 4 * i;       // 0..15
            size_t off = (size_t)(c0 + c) * HW + sub * 256 + 4 * tq;
            float4 qv = *(const float4 *)(qsm + c * QS + 4 * tq);
            float4 xv = *(const float4 *)(xb + off);
            *(float4 *)(qo + off) = qv;
            float4 sv;
            sv.x = __fadd_rn(__fsub_rn(qv.x, xv.x), xv.x);
            sv.y = __fadd_rn(__fsub_rn(qv.y, xv.y), xv.y);
            sv.z = __fadd_rn(__fsub_rn(qv.z, xv.z), xv.z);
            sv.w = __fadd_rn(__fsub_rn(qv.w, xv.w), xv.w);
            *(float4 *)(so + off) = sv;
        }
        __syncthreads();
    }
}

// =====================================================================
extern "C" void kernel_launch(void *const *d_in, const int *in_sizes, int n_in,
                              void *d_out, int out_size) {
    const float *x = (const float *)d_in[0];
    const float *w = (const float *)d_in[1];
    if (n_in >= 2 && in_sizes[0] == CODES * CDIM && in_sizes[1] == NPIX * CDIM) {
        const float *tmp = x; x = w; w = tmp;
    }
    float *out = (float *)d_out;
    float *out_idxf = out + 2 * (size_t)NPIX * CDIM;

    cudaFuncSetAttribute(mma_kernel, cudaFuncAttributeMaxDynamicSharedMemorySize, SMEM_MMA);

    prep_w<<<128, 256>>>(w);
    mma_kernel<<<512, 256, SMEM_MMA>>>(x, out_idxf);
    rescore2<<<1024, 256>>>(w, out_idxf);
    gather_kernel<<<dim3(16, 64), 256>>>(x, w, out);
}